// round 3
// baseline (speedup 1.0000x reference)
#include <cuda_runtime.h>
#include <cstdint>

// Problem constants
#define NROWS   64000      // B*T = 64*1000
#define TT      1000
#define INS     257
#define HID     40
#define NGATE   480        // 4 * 3*HID  (fwd L0, fwd L1, bwd L0, bwd L1)
#define KEXP    720        // 80 silu feats + 80*8 spline basis
#define OUTS    257

// GEMM tiling
#define BM 512
#define BN 32
#define BK 16
#define ASTR 520           // padded smem stride for A (16B-aligned rows, low bank conflict)
#define BSTR 36            // padded smem stride for B

// Scratch (static device globals — no allocation at runtime)
__device__ float g_gi[(size_t)NROWS * NGATE];   // 122.9 MB
__device__ float g_E [(size_t)NROWS * KEXP];    // 184.3 MB
__device__ float g_Wk[OUTS * KEXP];             // 0.74 MB

__device__ __forceinline__ float sigf(float x) { return 1.0f / (1.0f + __expf(-x)); }

// Cubic B-spline basis on the reference grid: grid[j] = 0.4*(j-3) - 1, j=0..11
__device__ __forceinline__ void bspline8(float x, float* o) {
    float bb[11];
#pragma unroll
    for (int j = 0; j < 11; j++) {
        float gA = 0.4f * (float)(j - 3) - 1.0f;
        float gB = 0.4f * (float)(j - 2) - 1.0f;
        bb[j] = (x >= gA && x < gB) ? 1.0f : 0.0f;
    }
#pragma unroll
    for (int k = 1; k <= 3; k++) {
        float inv = 1.0f / (0.4f * (float)k);
#pragma unroll
        for (int j = 0; j <= 10 - k; j++) {
            float gj = 0.4f * (float)(j - 3) - 1.0f;       // grid[j]
            float gk = 0.4f * (float)(j + k - 2) - 1.0f;   // grid[j+k+1]
            bb[j] = ((x - gj) * bb[j] + (gk - x) * bb[j + 1]) * inv;
        }
    }
#pragma unroll
    for (int m = 0; m < 8; m++) o[m] = bb[m];
}

// ---------------------------------------------------------------------------
// Kernel 0: fold spline_scaler into spline_weight and concat with base_weight
// Wk[o][k]: k<80 -> base_weight[o][k]; else -> spline_weight[o][i][m]*scaler[o][i]
// ---------------------------------------------------------------------------
__global__ void prep_wk_kernel(const float* __restrict__ base_w,
                               const float* __restrict__ spl_w,
                               const float* __restrict__ scaler) {
    int idx = blockIdx.x * 256 + threadIdx.x;
    if (idx >= OUTS * KEXP) return;
    int o = idx / KEXP, k = idx % KEXP;
    float v;
    if (k < 80) {
        v = base_w[o * 80 + k];
    } else {
        int q = k - 80;
        int i = q >> 3, m = q & 7;
        v = spl_w[(o * 80 + i) * 8 + m] * scaler[o * 80 + i];
    }
    g_Wk[idx] = v;
}

// ---------------------------------------------------------------------------
// Kernel 1: gi[64000, 480] = X[64000, 257] * Wcat[480, 257]^T
// Wcat rows: [Wih_f L0 (120), Wih_f L1 (120), Wih_b L0 (120), Wih_b L1 (120)]
// ---------------------------------------------------------------------------
__global__ __launch_bounds__(256, 2)
void gemm_gi_kernel(const float* __restrict__ X,
                    const float* __restrict__ Wf,   // (240, 257)
                    const float* __restrict__ Wb) { // (240, 257)
    __shared__ float As[BK * ASTR];
    __shared__ float Bs[BK * BSTR];

    const int n0 = blockIdx.x * BN;
    const int m0 = blockIdx.y * BM;
    const int tid = threadIdx.x;
    const int tn = tid & 3;    // 0..3  (8 cols each)
    const int tm = tid >> 2;   // 0..63 (8 rows each)

    float acc[8][8];
#pragma unroll
    for (int i = 0; i < 8; i++)
#pragma unroll
        for (int j = 0; j < 8; j++) acc[i][j] = 0.0f;

    const int K = INS;                 // 257
    for (int k0 = 0; k0 < 272; k0 += BK) {   // 17 tiles, zero-padded tail
        __syncthreads();
        // A tile: 512x16 = 8192 elems, 32 per thread (coalesced: e->(m,k))
#pragma unroll
        for (int i = 0; i < 32; i++) {
            int e = tid + i * 256;
            int m = e >> 4, k = e & 15;
            int kk = k0 + k;
            float v = (kk < K) ? X[(size_t)(m0 + m) * K + kk] : 0.0f;
            As[k * ASTR + m] = v;
        }
        // B tile: 32x16 = 512 elems, 2 per thread
#pragma unroll
        for (int i = 0; i < 2; i++) {
            int e = tid + i * 256;
            int n = e >> 4, k = e & 15;
            int kk = k0 + k;
            int g = n0 + n;
            float v = 0.0f;
            if (kk < K) v = (g < 240) ? Wf[g * K + kk] : Wb[(g - 240) * K + kk];
            Bs[k * BSTR + n] = v;
        }
        __syncthreads();
#pragma unroll
        for (int k = 0; k < BK; k++) {
            const float* ap = &As[k * ASTR + (tm << 3)];
            const float* bp = &Bs[k * BSTR + (tn << 3)];
            float4 a0 = *(const float4*)ap;
            float4 a1 = *(const float4*)(ap + 4);
            float4 b0 = *(const float4*)bp;
            float4 b1 = *(const float4*)(bp + 4);
            float av[8] = {a0.x, a0.y, a0.z, a0.w, a1.x, a1.y, a1.z, a1.w};
            float bv[8] = {b0.x, b0.y, b0.z, b0.w, b1.x, b1.y, b1.z, b1.w};
#pragma unroll
            for (int i = 0; i < 8; i++)
#pragma unroll
                for (int j = 0; j < 8; j++)
                    acc[i][j] = fmaf(av[i], bv[j], acc[i][j]);
        }
    }
#pragma unroll
    for (int i = 0; i < 8; i++) {
        int m = m0 + (tm << 3) + i;
        float* cp = &g_gi[(size_t)m * NGATE + n0 + (tn << 3)];
        *(float4*)cp       = make_float4(acc[i][0], acc[i][1], acc[i][2], acc[i][3]);
        *(float4*)(cp + 4) = make_float4(acc[i][4], acc[i][5], acc[i][6], acc[i][7]);
    }
}

// ---------------------------------------------------------------------------
// Kernel 2: per-row GRU cells (non-recurrent) + feature expansion into g_E
// Block = 256 threads = 4 rows x 64 lanes (lanes 0..39 active for unit math)
// ---------------------------------------------------------------------------
__global__ __launch_bounds__(256)
void feat_kernel(const float* __restrict__ bih_f, const float* __restrict__ bhh_f,
                 const float* __restrict__ bih_b, const float* __restrict__ bhh_b,
                 const float* __restrict__ Whh_f, const float* __restrict__ Whh_b) {
    __shared__ float sWf[40 * 120];   // Whh_f layer1, transposed: [j][g]
    __shared__ float sWb[40 * 120];   // Whh_b layer1, transposed
    __shared__ float sh1f[4][40];
    __shared__ float sh1b[4][40];

    const int tid = threadIdx.x;
    for (int e = tid; e < 4800; e += 256) {
        int g = e / 40, j = e % 40;
        sWf[j * 120 + g] = Whh_f[4800 + e];   // layer1 starts at 120*40
        sWb[j * 120 + g] = Whh_b[4800 + e];
    }
    __syncthreads();

    const int rl = tid >> 6;       // row within block, 0..3
    const int u  = tid & 63;       // unit lane
    const int row = blockIdx.x * 4 + rl;
    const int b = row / TT, t = row % TT;
    const int row_rev = b * TT + (TT - 1 - t);

    const float* gf = g_gi + (size_t)row * NGATE;
    const float* gb = g_gi + (size_t)row_rev * NGATE;

    float h1f = 0.0f, h1b = 0.0f;
    if (u < HID) {
        // fwd layer 0 (h=0 -> gh = bhh)
        {
            float ir = gf[u]        + bih_f[u];
            float iz = gf[40 + u]   + bih_f[40 + u];
            float in_ = gf[80 + u]  + bih_f[80 + u];
            float r = sigf(ir + bhh_f[u]);
            float z = sigf(iz + bhh_f[40 + u]);
            float n = tanhf(in_ + r * bhh_f[80 + u]);
            h1f = (1.0f - z) * n;
            sh1f[rl][u] = h1f;
        }
        // bwd layer 0 (gates 240..359 of the time-reversed row)
        {
            float ir = gb[240 + u]  + bih_b[u];
            float iz = gb[280 + u]  + bih_b[40 + u];
            float in_ = gb[320 + u] + bih_b[80 + u];
            float r = sigf(ir + bhh_b[u]);
            float z = sigf(iz + bhh_b[40 + u]);
            float n = tanhf(in_ + r * bhh_b[80 + u]);
            h1b = (1.0f - z) * n;
            sh1b[rl][u] = h1b;
        }
    }
    __syncthreads();

    if (u < HID) {
        // fwd layer 1
        float gr = bhh_f[120 + u], gz = bhh_f[160 + u], gn = bhh_f[200 + u];
#pragma unroll
        for (int j = 0; j < 40; j++) {
            float h = sh1f[rl][j];
            gr = fmaf(sWf[j * 120 + u],      h, gr);
            gz = fmaf(sWf[j * 120 + 40 + u], h, gz);
            gn = fmaf(sWf[j * 120 + 80 + u], h, gn);
        }
        float ir = gf[120 + u] + bih_f[120 + u];
        float iz = gf[160 + u] + bih_f[160 + u];
        float in_ = gf[200 + u] + bih_f[200 + u];
        float r = sigf(ir + gr);
        float z = sigf(iz + gz);
        float n = tanhf(in_ + r * gn);
        float hf = (1.0f - z) * n + z * h1f;

        // bwd layer 1 (gates 360..479 of the time-reversed row)
        float br = bhh_b[120 + u], bz = bhh_b[160 + u], bn = bhh_b[200 + u];
#pragma unroll
        for (int j = 0; j < 40; j++) {
            float h = sh1b[rl][j];
            br = fmaf(sWb[j * 120 + u],      h, br);
            bz = fmaf(sWb[j * 120 + 40 + u], h, bz);
            bn = fmaf(sWb[j * 120 + 80 + u], h, bn);
        }
        float ir2 = gb[360 + u] + bih_b[120 + u];
        float iz2 = gb[400 + u] + bih_b[160 + u];
        float in2 = gb[440 + u] + bih_b[200 + u];
        float r2 = sigf(ir2 + br);
        float z2 = sigf(iz2 + bz);
        float n2 = tanhf(in2 + r2 * bn);
        float hb = (1.0f - z2) * n2 + z2 * h1b;

        // Expanded features: [silu(feat), basis(feat)]
        float* e = g_E + (size_t)row * KEXP;
        e[u]      = hf * sigf(hf);
        e[40 + u] = hb * sigf(hb);

        float bf[8];
        bspline8(hf, bf);
        *(float4*)&e[80 + u * 8]     = make_float4(bf[0], bf[1], bf[2], bf[3]);
        *(float4*)&e[80 + u * 8 + 4] = make_float4(bf[4], bf[5], bf[6], bf[7]);
        bspline8(hb, bf);
        *(float4*)&e[80 + (40 + u) * 8]     = make_float4(bf[0], bf[1], bf[2], bf[3]);
        *(float4*)&e[80 + (40 + u) * 8 + 4] = make_float4(bf[4], bf[5], bf[6], bf[7]);
    }
}

// ---------------------------------------------------------------------------
// Kernel 3: out[64000, 257] = sigmoid-epilogue( E[64000,720] * Wk[257,720]^T )
// ---------------------------------------------------------------------------
__global__ __launch_bounds__(256, 2)
void gemm_kan_kernel(const float* __restrict__ slope, float* __restrict__ out) {
    __shared__ float As[BK * ASTR];
    __shared__ float Bs[BK * BSTR];

    const int n0 = blockIdx.x * BN;
    const int m0 = blockIdx.y * BM;
    const int tid = threadIdx.x;
    const int tn = tid & 3;
    const int tm = tid >> 2;

    float acc[8][8];
#pragma unroll
    for (int i = 0; i < 8; i++)
#pragma unroll
        for (int j = 0; j < 8; j++) acc[i][j] = 0.0f;

    for (int k0 = 0; k0 < KEXP; k0 += BK) {   // 45 tiles, 720 % 16 == 0
        __syncthreads();
#pragma unroll
        for (int i = 0; i < 32; i++) {
            int e = tid + i * 256;
            int m = e >> 4, k = e & 15;
            As[k * ASTR + m] = g_E[(size_t)(m0 + m) * KEXP + k0 + k];
        }
#pragma unroll
        for (int i = 0; i < 2; i++) {
            int e = tid + i * 256;
            int n = e >> 4, k = e & 15;
            int g = n0 + n;
            Bs[k * BSTR + n] = (g < OUTS) ? g_Wk[g * KEXP + k0 + k] : 0.0f;
        }
        __syncthreads();
#pragma unroll
        for (int k = 0; k < BK; k++) {
            const float* ap = &As[k * ASTR + (tm << 3)];
            const float* bp = &Bs[k * BSTR + (tn << 3)];
            float4 a0 = *(const float4*)ap;
            float4 a1 = *(const float4*)(ap + 4);
            float4 b0 = *(const float4*)bp;
            float4 b1 = *(const float4*)(bp + 4);
            float av[8] = {a0.x, a0.y, a0.z, a0.w, a1.x, a1.y, a1.z, a1.w};
            float bv[8] = {b0.x, b0.y, b0.z, b0.w, b1.x, b1.y, b1.z, b1.w};
#pragma unroll
            for (int i = 0; i < 8; i++)
#pragma unroll
                for (int j = 0; j < 8; j++)
                    acc[i][j] = fmaf(av[i], bv[j], acc[i][j]);
        }
    }
#pragma unroll
    for (int i = 0; i < 8; i++) {
        int m = m0 + (tm << 3) + i;
        float* op = out + (size_t)m * OUTS;
#pragma unroll
        for (int j = 0; j < 8; j++) {
            int o = n0 + (tn << 3) + j;
            if (o < OUTS) op[o] = 1.2f * sigf(slope[o] * acc[i][j]);
        }
    }
}

// ---------------------------------------------------------------------------
extern "C" void kernel_launch(void* const* d_in, const int* in_sizes, int n_in,
                              void* d_out, int out_size) {
    const float* x      = (const float*)d_in[0];
    const float* Wih_f  = (const float*)d_in[1];
    const float* Whh_f  = (const float*)d_in[2];
    const float* bih_f  = (const float*)d_in[3];
    const float* bhh_f  = (const float*)d_in[4];
    const float* Wih_b  = (const float*)d_in[5];
    const float* Whh_b  = (const float*)d_in[6];
    const float* bih_b  = (const float*)d_in[7];
    const float* bhh_b  = (const float*)d_in[8];
    const float* base_w = (const float*)d_in[9];
    const float* spl_w  = (const float*)d_in[10];
    const float* scaler = (const float*)d_in[11];
    const float* slope  = (const float*)d_in[12];
    // d_in[13] = lengths: unused by the reference (full-length sequences)
    float* out = (float*)d_out;

    prep_wk_kernel<<<(OUTS * KEXP + 255) / 256, 256>>>(base_w, spl_w, scaler);
    gemm_gi_kernel<<<dim3(NGATE / BN, NROWS / BM), 256>>>(x, Wih_f, Wih_b);
    feat_kernel<<<NROWS / 4, 256>>>(bih_f, bhh_f, bih_b, bhh_b, Whh_f, Whh_b);
    gemm_kan_kernel<<<dim3((OUTS + BN - 1) / BN, NROWS / BM), 256>>>(slope, out);
}

// round 5
// speedup vs baseline: 1.7302x; 1.7302x over previous
#include <cuda_runtime.h>
#include <cstdint>

// Problem constants
#define NROWS   64000      // B*T
#define TT      1000
#define INS     257
#define HID     40
#define NGATE   480
#define NGATE_P 512        // padded N for gate GEMM
#define KEXP    720
#define OUTS    257
#define OUTS_P  320        // padded N for KAN GEMM

#define TSTR    20         // smem tile row stride (conflict-free for frag pattern)

// Scratch (static device globals)
__device__ float g_gi[(size_t)NROWS * NGATE];    // 122.9 MB
__device__ float g_E [(size_t)NROWS * KEXP];     // 184.3 MB (tf32-rounded)
__device__ float g_Wk[OUTS_P * KEXP];            // tf32-rounded, zero-padded rows

__device__ __forceinline__ float sigf(float x) { return 1.0f / (1.0f + __expf(-x)); }
__device__ __forceinline__ unsigned tf32u(float v) {
    unsigned u; asm("cvt.rna.tf32.f32 %0, %1;" : "=r"(u) : "f"(v)); return u;
}
__device__ __forceinline__ float tf32f(float v) { return __uint_as_float(tf32u(v)); }

#define MMA8(C, A, B) \
    asm volatile("mma.sync.aligned.m16n8k8.row.col.f32.tf32.tf32.f32 " \
        "{%0,%1,%2,%3},{%4,%5,%6,%7},{%8,%9},{%0,%1,%2,%3};" \
        : "+f"(C[0]), "+f"(C[1]), "+f"(C[2]), "+f"(C[3]) \
        : "r"(A[0]), "r"(A[1]), "r"(A[2]), "r"(A[3]), "r"(B[0]), "r"(B[1]))

// Cubic B-spline basis: grid[j] = 0.4*(j-3) - 1
__device__ __forceinline__ void bspline8(float x, float* o) {
    float bb[11];
#pragma unroll
    for (int j = 0; j < 11; j++) {
        float gA = 0.4f * (float)(j - 3) - 1.0f;
        float gB = 0.4f * (float)(j - 2) - 1.0f;
        bb[j] = (x >= gA && x < gB) ? 1.0f : 0.0f;
    }
#pragma unroll
    for (int k = 1; k <= 3; k++) {
        float inv = 1.0f / (0.4f * (float)k);
#pragma unroll
        for (int j = 0; j <= 10 - k; j++) {
            float gj = 0.4f * (float)(j - 3) - 1.0f;
            float gk = 0.4f * (float)(j + k - 2) - 1.0f;
            bb[j] = ((x - gj) * bb[j] + (gk - x) * bb[j + 1]) * inv;
        }
    }
#pragma unroll
    for (int m = 0; m < 8; m++) o[m] = bb[m];
}

// ---------------------------------------------------------------------------
// Kernel 0: build padded, tf32-rounded Wk = [base_weight | spline_weight*scaler]
// ---------------------------------------------------------------------------
__global__ void prep_wk_kernel(const float* __restrict__ base_w,
                               const float* __restrict__ spl_w,
                               const float* __restrict__ scaler) {
    int idx = blockIdx.x * 256 + threadIdx.x;
    if (idx >= OUTS_P * KEXP) return;
    int o = idx / KEXP, k = idx % KEXP;
    float v = 0.0f;
    if (o < OUTS) {
        if (k < 80) {
            v = base_w[o * 80 + k];
        } else {
            int q = k - 80;
            int i = q >> 3, m = q & 7;
            v = spl_w[(o * 80 + i) * 8 + m] * scaler[o * 80 + i];
        }
    }
    g_Wk[idx] = tf32f(v);
}

// ---------------------------------------------------------------------------
// Kernel 1: gi[64000,480] = X[64000,257] * Wcat[480,257]^T   (3x tf32 MMA)
// ---------------------------------------------------------------------------
__global__ __launch_bounds__(256, 2)
void gemm_gi_kernel(const float* __restrict__ X,
                    const float* __restrict__ Wf,
                    const float* __restrict__ Wb) {
    extern __shared__ float sm[];
    float* Ah = sm;                    // 2 * 128*TSTR
    float* Al = Ah + 2 * 128 * TSTR;
    float* Bh = Al + 2 * 128 * TSTR;   // 2 * 64*TSTR
    float* Bl = Bh + 2 * 64 * TSTR;

    const int tid = threadIdx.x, lane = tid & 31, w = tid >> 5;
    const int g = lane >> 2, c = lane & 3;
    const int wm = (w >> 1) * 32, wn = (w & 1) * 32;
    const int n0 = blockIdx.x * 64, m0 = blockIdx.y * 128;

    float acc[2][4][4];
#pragma unroll
    for (int i = 0; i < 2; i++)
#pragma unroll
        for (int j = 0; j < 4; j++)
#pragma unroll
            for (int l = 0; l < 4; l++) acc[i][j][l] = 0.0f;

    // ---- stage helpers (inline) ----
    // A tile: 128x16, 2 elem-groups per thread (4 floats each, scalar loads)
    // B tile: 64x16, 1 elem-group per thread
    const int aM0 = (tid) >> 2,        aK0 = (tid & 3) * 4;
    const int aM1 = (tid + 256) >> 2,  aK1 = ((tid + 256) & 3) * 4;
    const int bN  = tid >> 2,          bK  = (tid & 3) * 4;

    float va0[4], va1[4], vb[4];
    // load tile 0
    {
        int k0 = 0;
#pragma unroll
        for (int j = 0; j < 4; j++) {
            va0[j] = X[(size_t)(m0 + aM0) * INS + k0 + aK0 + j];
            va1[j] = X[(size_t)(m0 + aM1) * INS + k0 + aK1 + j];
        }
        int gg = n0 + bN;
#pragma unroll
        for (int j = 0; j < 4; j++) vb[j] = 0.0f;
        if (gg < NGATE) {
            const float* src = (gg < 240) ? &Wf[(size_t)gg * INS] : &Wb[(size_t)(gg - 240) * INS];
#pragma unroll
            for (int j = 0; j < 4; j++) vb[j] = src[k0 + bK + j];
        }
#pragma unroll
        for (int j = 0; j < 4; j++) {
            float h0 = tf32f(va0[j]); Ah[aM0 * TSTR + aK0 + j] = h0; Al[aM0 * TSTR + aK0 + j] = tf32f(va0[j] - h0);
            float h1 = tf32f(va1[j]); Ah[aM1 * TSTR + aK1 + j] = h1; Al[aM1 * TSTR + aK1 + j] = tf32f(va1[j] - h1);
            float hb = tf32f(vb[j]);  Bh[bN  * TSTR + bK  + j] = hb; Bl[bN  * TSTR + bK  + j] = tf32f(vb[j] - hb);
        }
    }
    __syncthreads();

    const int NT = 17;   // ceil(257/16) tiles, last tile mostly padded
    for (int t = 0; t < NT; t++) {
        const int cur = t & 1;
        const bool pf = (t + 1) < NT;
        const int k0n = (t + 1) * 16;
        if (pf) {
            if (k0n < 256) {
#pragma unroll
                for (int j = 0; j < 4; j++) {
                    va0[j] = X[(size_t)(m0 + aM0) * INS + k0n + aK0 + j];
                    va1[j] = X[(size_t)(m0 + aM1) * INS + k0n + aK1 + j];
                }
            } else {  // k0n == 256: only k==256 valid
#pragma unroll
                for (int j = 0; j < 4; j++) { va0[j] = 0.0f; va1[j] = 0.0f; }
                if (aK0 == 0) va0[0] = X[(size_t)(m0 + aM0) * INS + 256];
                if (aK1 == 0) va1[0] = X[(size_t)(m0 + aM1) * INS + 256];
            }
            int gg = n0 + bN;
#pragma unroll
            for (int j = 0; j < 4; j++) vb[j] = 0.0f;
            if (gg < NGATE) {
                const float* src = (gg < 240) ? &Wf[(size_t)gg * INS] : &Wb[(size_t)(gg - 240) * INS];
                if (k0n < 256) {
#pragma unroll
                    for (int j = 0; j < 4; j++) vb[j] = src[k0n + bK + j];
                } else if (bK == 0) {
                    vb[0] = src[256];
                }
            }
        }

        // ---- compute current tile ----
        const float* Ahc = Ah + cur * 128 * TSTR;
        const float* Alc = Al + cur * 128 * TSTR;
        const float* Bhc = Bh + cur * 64 * TSTR;
        const float* Blc = Bl + cur * 64 * TSTR;
#pragma unroll
        for (int ks = 0; ks < 2; ks++) {
            const int col = ks * 8 + c;
            unsigned ah[2][4], al[2][4], bh[4][2], bl[4][2];
#pragma unroll
            for (int mt = 0; mt < 2; mt++) {
                const float* p = &Ahc[(wm + mt * 16 + g) * TSTR + col];
                ah[mt][0] = __float_as_uint(p[0]);
                ah[mt][1] = __float_as_uint(p[8 * TSTR]);
                ah[mt][2] = __float_as_uint(p[4]);
                ah[mt][3] = __float_as_uint(p[8 * TSTR + 4]);
                const float* q = &Alc[(wm + mt * 16 + g) * TSTR + col];
                al[mt][0] = __float_as_uint(q[0]);
                al[mt][1] = __float_as_uint(q[8 * TSTR]);
                al[mt][2] = __float_as_uint(q[4]);
                al[mt][3] = __float_as_uint(q[8 * TSTR + 4]);
            }
#pragma unroll
            for (int nt = 0; nt < 4; nt++) {
                const float* p = &Bhc[(wn + nt * 8 + g) * TSTR + col];
                bh[nt][0] = __float_as_uint(p[0]);
                bh[nt][1] = __float_as_uint(p[4]);
                const float* q = &Blc[(wn + nt * 8 + g) * TSTR + col];
                bl[nt][0] = __float_as_uint(q[0]);
                bl[nt][1] = __float_as_uint(q[4]);
            }
#pragma unroll
            for (int mt = 0; mt < 2; mt++)
#pragma unroll
                for (int nt = 0; nt < 4; nt++) {
                    MMA8(acc[mt][nt], ah[mt], bh[nt]);
                    MMA8(acc[mt][nt], al[mt], bh[nt]);
                    MMA8(acc[mt][nt], ah[mt], bl[nt]);
                }
        }

        if (pf) {
            const int nb = cur ^ 1;
            float* Ahn = Ah + nb * 128 * TSTR;
            float* Aln = Al + nb * 128 * TSTR;
            float* Bhn = Bh + nb * 64 * TSTR;
            float* Bln = Bl + nb * 64 * TSTR;
#pragma unroll
            for (int j = 0; j < 4; j++) {
                float h0 = tf32f(va0[j]); Ahn[aM0 * TSTR + aK0 + j] = h0; Aln[aM0 * TSTR + aK0 + j] = tf32f(va0[j] - h0);
                float h1 = tf32f(va1[j]); Ahn[aM1 * TSTR + aK1 + j] = h1; Aln[aM1 * TSTR + aK1 + j] = tf32f(va1[j] - h1);
                float hb = tf32f(vb[j]);  Bhn[bN  * TSTR + bK  + j] = hb; Bln[bN  * TSTR + bK  + j] = tf32f(vb[j] - hb);
            }
        }
        __syncthreads();
    }

    // ---- store ----
#pragma unroll
    for (int mt = 0; mt < 2; mt++)
#pragma unroll
        for (int nt = 0; nt < 4; nt++) {
            int r0 = m0 + wm + mt * 16 + g, r1 = r0 + 8;
            int o0 = n0 + wn + nt * 8 + 2 * c;
            float* C = acc[mt][nt];
            if (o0 < NGATE) {
                g_gi[(size_t)r0 * NGATE + o0] = C[0];
                g_gi[(size_t)r1 * NGATE + o0] = C[2];
                g_gi[(size_t)r0 * NGATE + o0 + 1] = C[1];
                g_gi[(size_t)r1 * NGATE + o0 + 1] = C[3];
            }
        }
}

// ---------------------------------------------------------------------------
// Kernel 2: per-row GRU cells + feature expansion into g_E (tf32-rounded)
// ---------------------------------------------------------------------------
__global__ __launch_bounds__(256)
void feat_kernel(const float* __restrict__ bih_f, const float* __restrict__ bhh_f,
                 const float* __restrict__ bih_b, const float* __restrict__ bhh_b,
                 const float* __restrict__ Whh_f, const float* __restrict__ Whh_b) {
    __shared__ float sWf[40 * 120];
    __shared__ float sWb[40 * 120];
    __shared__ float sh1f[4][40];
    __shared__ float sh1b[4][40];

    const int tid = threadIdx.x;
    for (int e = tid; e < 4800; e += 256) {
        int g = e / 40, j = e % 40;
        sWf[j * 120 + g] = Whh_f[4800 + e];
        sWb[j * 120 + g] = Whh_b[4800 + e];
    }
    __syncthreads();

    const int rl = tid >> 6;
    const int u  = tid & 63;
    const int row = blockIdx.x * 4 + rl;
    const int b = row / TT, t = row % TT;
    const int row_rev = b * TT + (TT - 1 - t);

    const float* gf = g_gi + (size_t)row * NGATE;
    const float* gb = g_gi + (size_t)row_rev * NGATE;

    float h1f = 0.0f, h1b = 0.0f;
    if (u < HID) {
        {
            float ir = gf[u]       + bih_f[u];
            float iz = gf[40 + u]  + bih_f[40 + u];
            float in_ = gf[80 + u] + bih_f[80 + u];
            float r = sigf(ir + bhh_f[u]);
            float z = sigf(iz + bhh_f[40 + u]);
            float n = tanhf(in_ + r * bhh_f[80 + u]);
            h1f = (1.0f - z) * n;
            sh1f[rl][u] = h1f;
        }
        {
            float ir = gb[240 + u]  + bih_b[u];
            float iz = gb[280 + u]  + bih_b[40 + u];
            float in_ = gb[320 + u] + bih_b[80 + u];
            float r = sigf(ir + bhh_b[u]);
            float z = sigf(iz + bhh_b[40 + u]);
            float n = tanhf(in_ + r * bhh_b[80 + u]);
            h1b = (1.0f - z) * n;
            sh1b[rl][u] = h1b;
        }
    }
    __syncthreads();

    if (u < HID) {
        float gr = bhh_f[120 + u], gz = bhh_f[160 + u], gn = bhh_f[200 + u];
#pragma unroll
        for (int j = 0; j < 40; j++) {
            float h = sh1f[rl][j];
            gr = fmaf(sWf[j * 120 + u],      h, gr);
            gz = fmaf(sWf[j * 120 + 40 + u], h, gz);
            gn = fmaf(sWf[j * 120 + 80 + u], h, gn);
        }
        float ir = gf[120 + u] + bih_f[120 + u];
        float iz = gf[160 + u] + bih_f[160 + u];
        float in_ = gf[200 + u] + bih_f[200 + u];
        float r = sigf(ir + gr);
        float z = sigf(iz + gz);
        float n = tanhf(in_ + r * gn);
        float hf = (1.0f - z) * n + z * h1f;

        float br = bhh_b[120 + u], bz = bhh_b[160 + u], bn = bhh_b[200 + u];
#pragma unroll
        for (int j = 0; j < 40; j++) {
            float h = sh1b[rl][j];
            br = fmaf(sWb[j * 120 + u],      h, br);
            bz = fmaf(sWb[j * 120 + 40 + u], h, bz);
            bn = fmaf(sWb[j * 120 + 80 + u], h, bn);
        }
        float ir2 = gb[360 + u] + bih_b[120 + u];
        float iz2 = gb[400 + u] + bih_b[160 + u];
        float in2 = gb[440 + u] + bih_b[200 + u];
        float r2 = sigf(ir2 + br);
        float z2 = sigf(iz2 + bz);
        float n2 = tanhf(in2 + r2 * bn);
        float hb = (1.0f - z2) * n2 + z2 * h1b;

        float* e = g_E + (size_t)row * KEXP;
        e[u]      = tf32f(hf * sigf(hf));
        e[40 + u] = tf32f(hb * sigf(hb));

        float bf[8];
        bspline8(hf, bf);
        *(float4*)&e[80 + u * 8]     = make_float4(tf32f(bf[0]), tf32f(bf[1]), tf32f(bf[2]), tf32f(bf[3]));
        *(float4*)&e[80 + u * 8 + 4] = make_float4(tf32f(bf[4]), tf32f(bf[5]), tf32f(bf[6]), tf32f(bf[7]));
        bspline8(hb, bf);
        *(float4*)&e[80 + (40 + u) * 8]     = make_float4(tf32f(bf[0]), tf32f(bf[1]), tf32f(bf[2]), tf32f(bf[3]));
        *(float4*)&e[80 + (40 + u) * 8 + 4] = make_float4(tf32f(bf[4]), tf32f(bf[5]), tf32f(bf[6]), tf32f(bf[7]));
    }
}

// ---------------------------------------------------------------------------
// Kernel 3: out = 1.2*sigmoid(slope * (E[64000,720] * Wk[320,720]^T))  (tf32)
// ---------------------------------------------------------------------------
__global__ __launch_bounds__(256)
void gemm_kan_kernel(const float* __restrict__ slope, float* __restrict__ out) {
    extern __shared__ float sm[];
    float* As = sm;                  // 2 * 128*TSTR
    float* Bs = sm + 2 * 128 * TSTR; // 2 * 64*TSTR

    const int tid = threadIdx.x, lane = tid & 31, w = tid >> 5;
    const int g = lane >> 2, c = lane & 3;
    const int wm = (w >> 1) * 32, wn = (w & 1) * 32;
    const int n0 = blockIdx.x * 64, m0 = blockIdx.y * 128;

    float acc[2][4][4];
#pragma unroll
    for (int i = 0; i < 2; i++)
#pragma unroll
        for (int j = 0; j < 4; j++)
#pragma unroll
            for (int l = 0; l < 4; l++) acc[i][j][l] = 0.0f;

    const int aM0 = tid >> 2,         aK0 = (tid & 3) * 4;
    const int aM1 = (tid + 256) >> 2, aK1 = ((tid + 256) & 3) * 4;
    const int bN  = tid >> 2,         bK  = (tid & 3) * 4;

    // stage tile 0
    {
        float4 a0 = *(const float4*)&g_E[(size_t)(m0 + aM0) * KEXP + aK0];
        float4 a1 = *(const float4*)&g_E[(size_t)(m0 + aM1) * KEXP + aK1];
        float4 b0 = *(const float4*)&g_Wk[(size_t)(n0 + bN) * KEXP + bK];
        *(float4*)&As[aM0 * TSTR + aK0] = a0;
        *(float4*)&As[aM1 * TSTR + aK1] = a1;
        *(float4*)&Bs[bN  * TSTR + bK ] = b0;
    }
    __syncthreads();

    const int NT = KEXP / 16;   // 45
    for (int t = 0; t < NT; t++) {
        const int cur = t & 1;
        const bool pf = (t + 1) < NT;
        const int k0n = (t + 1) * 16;
        float4 pa0, pa1, pb0;
        if (pf) {
            pa0 = *(const float4*)&g_E[(size_t)(m0 + aM0) * KEXP + k0n + aK0];
            pa1 = *(const float4*)&g_E[(size_t)(m0 + aM1) * KEXP + k0n + aK1];
            pb0 = *(const float4*)&g_Wk[(size_t)(n0 + bN) * KEXP + k0n + bK];
        }

        const float* Ac = As + cur * 128 * TSTR;
        const float* Bc = Bs + cur * 64 * TSTR;
#pragma unroll
        for (int ks = 0; ks < 2; ks++) {
            const int col = ks * 8 + c;
            unsigned a[2][4], b[4][2];
#pragma unroll
            for (int mt = 0; mt < 2; mt++) {
                const float* p = &Ac[(wm + mt * 16 + g) * TSTR + col];
                a[mt][0] = __float_as_uint(p[0]);
                a[mt][1] = __float_as_uint(p[8 * TSTR]);
                a[mt][2] = __float_as_uint(p[4]);
                a[mt][3] = __float_as_uint(p[8 * TSTR + 4]);
            }
#pragma unroll
            for (int nt = 0; nt < 4; nt++) {
                const float* p = &Bc[(wn + nt * 8 + g) * TSTR + col];
                b[nt][0] = __float_as_uint(p[0]);
                b[nt][1] = __float_as_uint(p[4]);
            }
#pragma unroll
            for (int mt = 0; mt < 2; mt++)
#pragma unroll
                for (int nt = 0; nt < 4; nt++)
                    MMA8(acc[mt][nt], a[mt], b[nt]);
        }

        if (pf) {
            const int nb = cur ^ 1;
            *(float4*)&As[nb * 128 * TSTR + aM0 * TSTR + aK0] = pa0;
            *(float4*)&As[nb * 128 * TSTR + aM1 * TSTR + aK1] = pa1;
            *(float4*)&Bs[nb * 64  * TSTR + bN  * TSTR + bK ] = pb0;
        }
        __syncthreads();
    }

    // epilogue: 1.2 * sigmoid(slope * acc), masked to 257 cols
#pragma unroll
    for (int mt = 0; mt < 2; mt++)
#pragma unroll
        for (int nt = 0; nt < 4; nt++) {
            int r0 = m0 + wm + mt * 16 + g, r1 = r0 + 8;
            int o0 = n0 + wn + nt * 8 + 2 * c;
            float* C = acc[mt][nt];
            if (o0 < OUTS) {
                float s = __ldg(&slope[o0]);
                out[(size_t)r0 * OUTS + o0] = 1.2f * sigf(s * C[0]);
                out[(size_t)r1 * OUTS + o0] = 1.2f * sigf(s * C[2]);
            }
            if (o0 + 1 < OUTS) {
                float s = __ldg(&slope[o0 + 1]);
                out[(size_t)r0 * OUTS + o0 + 1] = 1.2f * sigf(s * C[1]);
                out[(size_t)r1 * OUTS + o0 + 1] = 1.2f * sigf(s * C[3]);
            }
        }
}

// ---------------------------------------------------------------------------
extern "C" void kernel_launch(void* const* d_in, const int* in_sizes, int n_in,
                              void* d_out, int out_size) {
    const float* x      = (const float*)d_in[0];
    const float* Wih_f  = (const float*)d_in[1];
    const float* Whh_f  = (const float*)d_in[2];
    const float* bih_f  = (const float*)d_in[3];
    const float* bhh_f  = (const float*)d_in[4];
    const float* Wih_b  = (const float*)d_in[5];
    const float* Whh_b  = (const float*)d_in[6];
    const float* bih_b  = (const float*)d_in[7];
    const float* bhh_b  = (const float*)d_in[8];
    const float* base_w = (const float*)d_in[9];
    const float* spl_w  = (const float*)d_in[10];
    const float* scaler = (const float*)d_in[11];
    const float* slope  = (const float*)d_in[12];
    float* out = (float*)d_out;

    const int GI_SMEM  = (2 * 128 * TSTR * 2 + 2 * 64 * TSTR * 2) * 4;  // 61440 B
    const int KAN_SMEM = (2 * 128 * TSTR + 2 * 64 * TSTR) * 4;          // 30720 B

    cudaFuncSetAttribute(gemm_gi_kernel,  cudaFuncAttributeMaxDynamicSharedMemorySize, GI_SMEM);
    cudaFuncSetAttribute(gemm_kan_kernel, cudaFuncAttributeMaxDynamicSharedMemorySize, KAN_SMEM);

    prep_wk_kernel<<<(OUTS_P * KEXP + 255) / 256, 256>>>(base_w, spl_w, scaler);
    gemm_gi_kernel<<<dim3(NGATE_P / 64, NROWS / 128), 256, GI_SMEM>>>(x, Wih_f, Wih_b);
    feat_kernel<<<NROWS / 4, 256>>>(bih_f, bhh_f, bih_b, bhh_b, Whh_f, Whh_b);
    gemm_kan_kernel<<<dim3(OUTS_P / 64, NROWS / 128), 256, KAN_SMEM>>>(slope, out);
}

// round 6
// speedup vs baseline: 2.1183x; 1.2243x over previous
#include <cuda_runtime.h>
#include <cuda_bf16.h>
#include <cstdint>

// Problem constants
#define NROWS   64000      // B*T
#define TT      1000
#define INS     257
#define KP      272        // padded K for gate GEMM
#define XSTR    544        // Xe row stride in bf16: [hi 272 | lo 272]
#define HID     40
#define NGATE   480
#define NGP     512        // padded N for gate GEMM
#define KEXP    720
#define OUTS    257
#define OUTP    384        // padded N for KAN GEMM (3 blocks of 128)

// gi smem geometry (bf16): row stride 40 bf16 = 80B (16 hi | 16 lo | 8 pad)
#define GA_ELEMS (256 * 40)
#define GB_ELEMS (128 * 40)
// kan smem geometry (f32): row stride 20 floats = 80B (16 data | 4 pad)
#define KA_ELEMS (256 * 20)
#define KB_ELEMS (128 * 20)
#define GEMM_SMEM 61440    // bytes, both kernels

// Static device scratch
__device__ __nv_bfloat16 g_Xe[(size_t)NROWS * XSTR];   // 69.6 MB
__device__ __nv_bfloat16 g_Wg[(size_t)NGP * XSTR];     // hi|lo gate weights, padded
__device__ float g_gi[(size_t)NROWS * NGATE];          // 122.9 MB
__device__ float g_E [(size_t)NROWS * KEXP];           // 184.3 MB (tf32-rounded)
__device__ float g_Wk[OUTP * KEXP];                    // tf32-rounded, padded

__device__ __forceinline__ float sigf(float x) { return 1.0f / (1.0f + __expf(-x)); }
__device__ __forceinline__ unsigned tf32u(float v) {
    unsigned u; asm("cvt.rna.tf32.f32 %0, %1;" : "=r"(u) : "f"(v)); return u;
}
__device__ __forceinline__ float tf32f(float v) { return __uint_as_float(tf32u(v)); }

#define MMAT(C, A, B) \
    asm volatile("mma.sync.aligned.m16n8k8.row.col.f32.tf32.tf32.f32 " \
        "{%0,%1,%2,%3},{%4,%5,%6,%7},{%8,%9},{%0,%1,%2,%3};" \
        : "+f"(C[0]), "+f"(C[1]), "+f"(C[2]), "+f"(C[3]) \
        : "r"(A[0]), "r"(A[1]), "r"(A[2]), "r"(A[3]), "r"(B[0]), "r"(B[1]))

#define MMAB(C, A, B) \
    asm volatile("mma.sync.aligned.m16n8k16.row.col.f32.bf16.bf16.f32 " \
        "{%0,%1,%2,%3},{%4,%5,%6,%7},{%8,%9},{%0,%1,%2,%3};" \
        : "+f"(C[0]), "+f"(C[1]), "+f"(C[2]), "+f"(C[3]) \
        : "r"(A[0]), "r"(A[1]), "r"(A[2]), "r"(A[3]), "r"(B[0]), "r"(B[1]))

// Cubic B-spline basis: grid[j] = 0.4*(j-3) - 1
__device__ __forceinline__ void bspline8(float x, float* o) {
    float bb[11];
#pragma unroll
    for (int j = 0; j < 11; j++) {
        float gA = 0.4f * (float)(j - 3) - 1.0f;
        float gB = 0.4f * (float)(j - 2) - 1.0f;
        bb[j] = (x >= gA && x < gB) ? 1.0f : 0.0f;
    }
#pragma unroll
    for (int k = 1; k <= 3; k++) {
        float inv = 1.0f / (0.4f * (float)k);
#pragma unroll
        for (int j = 0; j <= 10 - k; j++) {
            float gj = 0.4f * (float)(j - 3) - 1.0f;
            float gk = 0.4f * (float)(j + k - 2) - 1.0f;
            bb[j] = ((x - gj) * bb[j] + (gk - x) * bb[j + 1]) * inv;
        }
    }
#pragma unroll
    for (int m = 0; m < 8; m++) o[m] = bb[m];
}

// ---------------------------------------------------------------------------
// Prep: split X into bf16 hi|lo planes (padded K)
// ---------------------------------------------------------------------------
__global__ void prep_xe_kernel(const float* __restrict__ X) {
    int idx = blockIdx.x * 256 + threadIdx.x;
    if (idx >= NROWS * KP) return;
    int m = idx / KP, k = idx % KP;
    float v = (k < INS) ? X[(size_t)m * INS + k] : 0.0f;
    __nv_bfloat16 hi = __float2bfloat16_rn(v);
    __nv_bfloat16 lo = __float2bfloat16_rn(v - __bfloat162float(hi));
    g_Xe[(size_t)m * XSTR + k]       = hi;
    g_Xe[(size_t)m * XSTR + 272 + k] = lo;
}

// Prep: concat + split gate weights into bf16 hi|lo planes (padded N, K)
__global__ void prep_wg_kernel(const float* __restrict__ Wf,
                               const float* __restrict__ Wb) {
    int idx = blockIdx.x * 256 + threadIdx.x;
    if (idx >= NGP * KP) return;
    int g = idx / KP, k = idx % KP;
    float v = 0.0f;
    if (g < NGATE && k < INS)
        v = (g < 240) ? Wf[(size_t)g * INS + k] : Wb[(size_t)(g - 240) * INS + k];
    __nv_bfloat16 hi = __float2bfloat16_rn(v);
    __nv_bfloat16 lo = __float2bfloat16_rn(v - __bfloat162float(hi));
    g_Wg[(size_t)g * XSTR + k]       = hi;
    g_Wg[(size_t)g * XSTR + 272 + k] = lo;
}

// Prep: padded tf32-rounded Wk = [base_weight | spline_weight*scaler]
__global__ void prep_wk_kernel(const float* __restrict__ base_w,
                               const float* __restrict__ spl_w,
                               const float* __restrict__ scaler) {
    int idx = blockIdx.x * 256 + threadIdx.x;
    if (idx >= OUTP * KEXP) return;
    int o = idx / KEXP, k = idx % KEXP;
    float v = 0.0f;
    if (o < OUTS) {
        if (k < 80) v = base_w[o * 80 + k];
        else {
            int q = k - 80;
            int i = q >> 3, m = q & 7;
            v = spl_w[(o * 80 + i) * 8 + m] * scaler[o * 80 + i];
        }
    }
    g_Wk[idx] = tf32f(v);
}

// ---------------------------------------------------------------------------
// Kernel 1: gi = X * Wcat^T  (bf16 3-term split, 256x128 block, 64x64 warps)
// ---------------------------------------------------------------------------
__global__ __launch_bounds__(256, 1)
void gemm_gi_kernel() {
    extern __shared__ __nv_bfloat16 smb[];
    __nv_bfloat16* As = smb;                 // 2 * GA_ELEMS
    __nv_bfloat16* Bs = smb + 2 * GA_ELEMS;  // 2 * GB_ELEMS

    const int tid = threadIdx.x, lane = tid & 31, w = tid >> 5;
    const int g = lane >> 2, c = lane & 3;
    const int wm = (w >> 1) * 64, wn = (w & 1) * 64;
    const int n0 = blockIdx.x * 128, m0 = blockIdx.y * 256;

    float acc[4][8][4];
#pragma unroll
    for (int i = 0; i < 4; i++)
#pragma unroll
        for (int j = 0; j < 8; j++)
#pragma unroll
            for (int l = 0; l < 4; l++) acc[i][j][l] = 0.0f;

    // ---- stage tile 0 ----
    {
        const uint4* sH = (const uint4*)(g_Xe + (size_t)(m0 + tid) * XSTR);
        const uint4* sL = (const uint4*)(g_Xe + (size_t)(m0 + tid) * XSTR + 272);
        uint4* dA = (uint4*)(As + tid * 40);
        dA[0] = sH[0]; dA[1] = sH[1]; dA[2] = sL[0]; dA[3] = sL[1];
        if (tid < 128) {
            const uint4* bH = (const uint4*)(g_Wg + (size_t)(n0 + tid) * XSTR);
            const uint4* bL = (const uint4*)(g_Wg + (size_t)(n0 + tid) * XSTR + 272);
            uint4* dB = (uint4*)(Bs + tid * 40);
            dB[0] = bH[0]; dB[1] = bH[1]; dB[2] = bL[0]; dB[3] = bL[1];
        }
    }
    __syncthreads();

    const int NT = KP / 16;   // 17
    for (int t = 0; t < NT; t++) {
        const int cur = t & 1;
        const bool pf = (t + 1) < NT;
        uint4 ph0, ph1, pl0, pl1, qh0, qh1, ql0, ql1;
        if (pf) {
            const int k0 = (t + 1) * 16;
            const uint4* sH = (const uint4*)(g_Xe + (size_t)(m0 + tid) * XSTR + k0);
            const uint4* sL = (const uint4*)(g_Xe + (size_t)(m0 + tid) * XSTR + 272 + k0);
            ph0 = sH[0]; ph1 = sH[1]; pl0 = sL[0]; pl1 = sL[1];
            if (tid < 128) {
                const uint4* bH = (const uint4*)(g_Wg + (size_t)(n0 + tid) * XSTR + k0);
                const uint4* bL = (const uint4*)(g_Wg + (size_t)(n0 + tid) * XSTR + 272 + k0);
                qh0 = bH[0]; qh1 = bH[1]; ql0 = bL[0]; ql1 = bL[1];
            }
        }

        // ---- compute ----
        const unsigned* Aw = (const unsigned*)(As + cur * GA_ELEMS);
        const unsigned* Bw = (const unsigned*)(Bs + cur * GB_ELEMS);
        unsigned Ah[4][4], Al[4][4];
#pragma unroll
        for (int mt = 0; mt < 4; mt++) {
            const unsigned* p0 = Aw + (wm + mt * 16 + g) * 20;
            const unsigned* p1 = p0 + 8 * 20;
            Ah[mt][0] = p0[c];     Ah[mt][1] = p1[c];
            Ah[mt][2] = p0[c + 4]; Ah[mt][3] = p1[c + 4];
            Al[mt][0] = p0[8 + c];  Al[mt][1] = p1[8 + c];
            Al[mt][2] = p0[12 + c]; Al[mt][3] = p1[12 + c];
        }
#pragma unroll
        for (int nt = 0; nt < 8; nt++) {
            const unsigned* q = Bw + (wn + nt * 8 + g) * 20;
            unsigned bh[2] = {q[c], q[c + 4]};
            unsigned bl[2] = {q[8 + c], q[12 + c]};
#pragma unroll
            for (int mt = 0; mt < 4; mt++) {
                MMAB(acc[mt][nt], Ah[mt], bh);
                MMAB(acc[mt][nt], Al[mt], bh);
                MMAB(acc[mt][nt], Ah[mt], bl);
            }
        }

        if (pf) {
            const int nb = cur ^ 1;
            uint4* dA = (uint4*)(As + nb * GA_ELEMS + tid * 40);
            dA[0] = ph0; dA[1] = ph1; dA[2] = pl0; dA[3] = pl1;
            if (tid < 128) {
                uint4* dB = (uint4*)(Bs + nb * GB_ELEMS + tid * 40);
                dB[0] = qh0; dB[1] = qh1; dB[2] = ql0; dB[3] = ql1;
            }
        }
        __syncthreads();
    }

    // ---- store (mask n < 480) ----
#pragma unroll
    for (int mt = 0; mt < 4; mt++) {
        int r0 = m0 + wm + mt * 16 + g, r1 = r0 + 8;
#pragma unroll
        for (int nt = 0; nt < 8; nt++) {
            int o = n0 + wn + nt * 8 + 2 * c;
            if (o < NGATE) {
                float* C = acc[mt][nt];
                *(float2*)&g_gi[(size_t)r0 * NGATE + o] = make_float2(C[0], C[1]);
                *(float2*)&g_gi[(size_t)r1 * NGATE + o] = make_float2(C[2], C[3]);
            }
        }
    }
}

// ---------------------------------------------------------------------------
// Kernel 2: per-row GRU cells + feature expansion (16 rows/block)
// ---------------------------------------------------------------------------
__global__ __launch_bounds__(256)
void feat_kernel(const float* __restrict__ bih_f, const float* __restrict__ bhh_f,
                 const float* __restrict__ bih_b, const float* __restrict__ bhh_b,
                 const float* __restrict__ Whh_f, const float* __restrict__ Whh_b) {
    __shared__ float sWf[40 * 120];
    __shared__ float sWb[40 * 120];
    __shared__ float sh1f[4][40];
    __shared__ float sh1b[4][40];

    const int tid = threadIdx.x;
    for (int e = tid; e < 4800; e += 256) {
        int g = e / 40, j = e % 40;
        sWf[j * 120 + g] = Whh_f[4800 + e];
        sWb[j * 120 + g] = Whh_b[4800 + e];
    }
    __syncthreads();

    const int rl = tid >> 6;
    const int u  = tid & 63;
    const bool act = (u < HID);

    float bf_r0=0, bf_z0=0, bf_n0=0, bb_r0=0, bb_z0=0, bb_n0=0;
    float if_r0=0, if_z0=0, if_n0=0, ib_r0=0, ib_z0=0, ib_n0=0;
    float bf_r1=0, bf_z1=0, bf_n1=0, bb_r1=0, bb_z1=0, bb_n1=0;
    float if_r1=0, if_z1=0, if_n1=0, ib_r1=0, ib_z1=0, ib_n1=0;
    if (act) {
        bf_r0 = bhh_f[u]; bf_z0 = bhh_f[40+u]; bf_n0 = bhh_f[80+u];
        bb_r0 = bhh_b[u]; bb_z0 = bhh_b[40+u]; bb_n0 = bhh_b[80+u];
        if_r0 = bih_f[u]; if_z0 = bih_f[40+u]; if_n0 = bih_f[80+u];
        ib_r0 = bih_b[u]; ib_z0 = bih_b[40+u]; ib_n0 = bih_b[80+u];
        bf_r1 = bhh_f[120+u]; bf_z1 = bhh_f[160+u]; bf_n1 = bhh_f[200+u];
        bb_r1 = bhh_b[120+u]; bb_z1 = bhh_b[160+u]; bb_n1 = bhh_b[200+u];
        if_r1 = bih_f[120+u]; if_z1 = bih_f[160+u]; if_n1 = bih_f[200+u];
        ib_r1 = bih_b[120+u]; ib_z1 = bih_b[160+u]; ib_n1 = bih_b[200+u];
    }

    for (int it = 0; it < 4; it++) {
        const int row = blockIdx.x * 16 + it * 4 + rl;
        const int b = row / TT, t = row % TT;
        const int row_rev = b * TT + (TT - 1 - t);
        const float* gf = g_gi + (size_t)row * NGATE;
        const float* gb = g_gi + (size_t)row_rev * NGATE;

        float h1f = 0.0f, h1b = 0.0f;
        if (act) {
            {
                float r = sigf(gf[u] + if_r0 + bf_r0);
                float z = sigf(gf[40 + u] + if_z0 + bf_z0);
                float n = tanhf(gf[80 + u] + if_n0 + r * bf_n0);
                h1f = (1.0f - z) * n;
                sh1f[rl][u] = h1f;
            }
            {
                float r = sigf(gb[240 + u] + ib_r0 + bb_r0);
                float z = sigf(gb[280 + u] + ib_z0 + bb_z0);
                float n = tanhf(gb[320 + u] + ib_n0 + r * bb_n0);
                h1b = (1.0f - z) * n;
                sh1b[rl][u] = h1b;
            }
        }
        __syncthreads();

        if (act) {
            float gr = bf_r1, gz = bf_z1, gn = bf_n1;
#pragma unroll
            for (int j = 0; j < 40; j++) {
                float h = sh1f[rl][j];
                gr = fmaf(sWf[j * 120 + u],      h, gr);
                gz = fmaf(sWf[j * 120 + 40 + u], h, gz);
                gn = fmaf(sWf[j * 120 + 80 + u], h, gn);
            }
            float r = sigf(gf[120 + u] + if_r1 + gr);
            float z = sigf(gf[160 + u] + if_z1 + gz);
            float n = tanhf(gf[200 + u] + if_n1 + r * gn);
            float hf = (1.0f - z) * n + z * h1f;

            float br = bb_r1, bz = bb_z1, bn = bb_n1;
#pragma unroll
            for (int j = 0; j < 40; j++) {
                float h = sh1b[rl][j];
                br = fmaf(sWb[j * 120 + u],      h, br);
                bz = fmaf(sWb[j * 120 + 40 + u], h, bz);
                bn = fmaf(sWb[j * 120 + 80 + u], h, bn);
            }
            float r2 = sigf(gb[360 + u] + ib_r1 + br);
            float z2 = sigf(gb[400 + u] + ib_z1 + bz);
            float n2 = tanhf(gb[440 + u] + ib_n1 + r2 * bn);
            float hb = (1.0f - z2) * n2 + z2 * h1b;

            float* e = g_E + (size_t)row * KEXP;
            e[u]      = tf32f(hf * sigf(hf));
            e[40 + u] = tf32f(hb * sigf(hb));

            float bf[8];
            bspline8(hf, bf);
            *(float4*)&e[80 + u * 8]     = make_float4(tf32f(bf[0]), tf32f(bf[1]), tf32f(bf[2]), tf32f(bf[3]));
            *(float4*)&e[80 + u * 8 + 4] = make_float4(tf32f(bf[4]), tf32f(bf[5]), tf32f(bf[6]), tf32f(bf[7]));
            bspline8(hb, bf);
            *(float4*)&e[80 + (40 + u) * 8]     = make_float4(tf32f(bf[0]), tf32f(bf[1]), tf32f(bf[2]), tf32f(bf[3]));
            *(float4*)&e[80 + (40 + u) * 8 + 4] = make_float4(tf32f(bf[4]), tf32f(bf[5]), tf32f(bf[6]), tf32f(bf[7]));
        }
        __syncthreads();
    }
}

// ---------------------------------------------------------------------------
// Kernel 3: out = 1.2*sigmoid(slope * (E * Wk^T))   (tf32, 256x128, 64x64)
// ---------------------------------------------------------------------------
__global__ __launch_bounds__(256, 1)
void gemm_kan_kernel(const float* __restrict__ slope, float* __restrict__ out) {
    extern __shared__ float smf[];
    float* As = smf;                  // 2 * KA_ELEMS
    float* Bs = smf + 2 * KA_ELEMS;   // 2 * KB_ELEMS

    const int tid = threadIdx.x, lane = tid & 31, w = tid >> 5;
    const int g = lane >> 2, c = lane & 3;
    const int wm = (w >> 1) * 64, wn = (w & 1) * 64;
    const int n0 = blockIdx.x * 128, m0 = blockIdx.y * 256;

    float acc[4][8][4];
#pragma unroll
    for (int i = 0; i < 4; i++)
#pragma unroll
        for (int j = 0; j < 8; j++)
#pragma unroll
            for (int l = 0; l < 4; l++) acc[i][j][l] = 0.0f;

    // stage tile 0
    {
        const uint4* sA = (const uint4*)(g_E + (size_t)(m0 + tid) * KEXP);
        uint4* dA = (uint4*)(As + tid * 20);
        dA[0] = sA[0]; dA[1] = sA[1]; dA[2] = sA[2]; dA[3] = sA[3];
        if (tid < 128) {
            const uint4* sB = (const uint4*)(g_Wk + (size_t)(n0 + tid) * KEXP);
            uint4* dB = (uint4*)(Bs + tid * 20);
            dB[0] = sB[0]; dB[1] = sB[1]; dB[2] = sB[2]; dB[3] = sB[3];
        }
    }
    __syncthreads();

    const int NT = KEXP / 16;   // 45
    for (int t = 0; t < NT; t++) {
        const int cur = t & 1;
        const bool pf = (t + 1) < NT;
        uint4 pa0, pa1, pa2, pa3, pb0, pb1, pb2, pb3;
        if (pf) {
            const int k0 = (t + 1) * 16;
            const uint4* sA = (const uint4*)(g_E + (size_t)(m0 + tid) * KEXP + k0);
            pa0 = sA[0]; pa1 = sA[1]; pa2 = sA[2]; pa3 = sA[3];
            if (tid < 128) {
                const uint4* sB = (const uint4*)(g_Wk + (size_t)(n0 + tid) * KEXP + k0);
                pb0 = sB[0]; pb1 = sB[1]; pb2 = sB[2]; pb3 = sB[3];
            }
        }

        const float* Ac = As + cur * KA_ELEMS;
        const float* Bc = Bs + cur * KB_ELEMS;
#pragma unroll
        for (int ks = 0; ks < 2; ks++) {
            const int kc = ks * 8 + c;
            unsigned a[4][4];
#pragma unroll
            for (int mt = 0; mt < 4; mt++) {
                const float* p0 = Ac + (wm + mt * 16 + g) * 20;
                const float* p1 = p0 + 8 * 20;
                a[mt][0] = __float_as_uint(p0[kc]);
                a[mt][1] = __float_as_uint(p1[kc]);
                a[mt][2] = __float_as_uint(p0[kc + 4]);
                a[mt][3] = __float_as_uint(p1[kc + 4]);
            }
#pragma unroll
            for (int nt = 0; nt < 8; nt++) {
                const float* q = Bc + (wn + nt * 8 + g) * 20;
                unsigned b[2] = {__float_as_uint(q[kc]), __float_as_uint(q[kc + 4])};
#pragma unroll
                for (int mt = 0; mt < 4; mt++)
                    MMAT(acc[mt][nt], a[mt], b);
            }
        }

        if (pf) {
            const int nb = cur ^ 1;
            uint4* dA = (uint4*)(As + nb * KA_ELEMS + tid * 20);
            dA[0] = pa0; dA[1] = pa1; dA[2] = pa2; dA[3] = pa3;
            if (tid < 128) {
                uint4* dB = (uint4*)(Bs + nb * KB_ELEMS + tid * 20);
                dB[0] = pb0; dB[1] = pb1; dB[2] = pb2; dB[3] = pb3;
            }
        }
        __syncthreads();
    }

    // epilogue
#pragma unroll
    for (int mt = 0; mt < 4; mt++) {
        int r0 = m0 + wm + mt * 16 + g, r1 = r0 + 8;
#pragma unroll
        for (int nt = 0; nt < 8; nt++) {
            int o = n0 + wn + nt * 8 + 2 * c;
            float* C = acc[mt][nt];
            if (o < OUTS) {
                float s = __ldg(&slope[o]);
                out[(size_t)r0 * OUTS + o] = 1.2f * sigf(s * C[0]);
                out[(size_t)r1 * OUTS + o] = 1.2f * sigf(s * C[2]);
            }
            if (o + 1 < OUTS) {
                float s = __ldg(&slope[o + 1]);
                out[(size_t)r0 * OUTS + o + 1] = 1.2f * sigf(s * C[1]);
                out[(size_t)r1 * OUTS + o + 1] = 1.2f * sigf(s * C[3]);
            }
        }
    }
}

// ---------------------------------------------------------------------------
extern "C" void kernel_launch(void* const* d_in, const int* in_sizes, int n_in,
                              void* d_out, int out_size) {
    const float* x      = (const float*)d_in[0];
    const float* Wih_f  = (const float*)d_in[1];
    const float* Whh_f  = (const float*)d_in[2];
    const float* bih_f  = (const float*)d_in[3];
    const float* bhh_f  = (const float*)d_in[4];
    const float* Wih_b  = (const float*)d_in[5];
    const float* Whh_b  = (const float*)d_in[6];
    const float* bih_b  = (const float*)d_in[7];
    const float* bhh_b  = (const float*)d_in[8];
    const float* base_w = (const float*)d_in[9];
    const float* spl_w  = (const float*)d_in[10];
    const float* scaler = (const float*)d_in[11];
    const float* slope  = (const float*)d_in[12];
    float* out = (float*)d_out;

    cudaFuncSetAttribute(gemm_gi_kernel,  cudaFuncAttributeMaxDynamicSharedMemorySize, GEMM_SMEM);
    cudaFuncSetAttribute(gemm_kan_kernel, cudaFuncAttributeMaxDynamicSharedMemorySize, GEMM_SMEM);

    prep_xe_kernel<<<(NROWS * KP + 255) / 256, 256>>>(x);
    prep_wg_kernel<<<(NGP * KP + 255) / 256, 256>>>(Wih_f, Wih_b);
    prep_wk_kernel<<<(OUTP * KEXP + 255) / 256, 256>>>(base_w, spl_w, scaler);

    gemm_gi_kernel<<<dim3(NGP / 128, NROWS / 256), 256, GEMM_SMEM>>>();
    feat_kernel<<<NROWS / 16, 256>>>(bih_f, bhh_f, bih_b, bhh_b, Whh_f, Whh_b);
    gemm_kan_kernel<<<dim3(OUTP / 128, NROWS / 256), 256, GEMM_SMEM>>>(slope, out);
}

// round 7
// speedup vs baseline: 2.5165x; 1.1880x over previous
#include <cuda_runtime.h>
#include <cuda_bf16.h>
#include <cstdint>

// Problem constants
#define NROWS   64000      // B*T
#define TT      1000
#define INS     257
#define KP      272        // padded K for gate GEMM
#define XSTR    544        // Xe row stride in bf16: [hi 272 | lo 272]
#define HID     40
#define NGATE   480
#define NGP     512        // padded N for gate GEMM
#define KEXP    720
#define OUTS    257
#define OUTN    256        // KAN GEMM covers cols 0..255; col 256 fused into feat

// gi smem (bf16): per stage A 256x40, B 128x40
#define GA 10240
#define GB 5120
#define GI_STG (GA + GB)
// kan smem (f32): per stage A 256x20, B 128x20
#define KA 5120
#define KB 2560
#define KAN_STG (KA + KB)
#define SMEM_BYTES 122880  // 4 stages, both kernels

// Static device scratch
__device__ __nv_bfloat16 g_Xe[(size_t)NROWS * XSTR];   // 69.6 MB
__device__ __nv_bfloat16 g_Wg[(size_t)NGP * XSTR];
__device__ float g_gi[(size_t)NROWS * NGATE];          // 122.9 MB
__device__ float g_E [(size_t)NROWS * KEXP];           // 184.3 MB (tf32-rounded)
__device__ float g_Wk[(size_t)OUTS * KEXP];            // tf32-rounded, 257 rows

__device__ __forceinline__ float sigf(float x) { return 1.0f / (1.0f + __expf(-x)); }
__device__ __forceinline__ unsigned tf32u(float v) {
    unsigned u; asm("cvt.rna.tf32.f32 %0, %1;" : "=r"(u) : "f"(v)); return u;
}
__device__ __forceinline__ float tf32f(float v) { return __uint_as_float(tf32u(v)); }

__device__ __forceinline__ void cp16(uint32_t dst, const void* src) {
    asm volatile("cp.async.cg.shared.global [%0], [%1], 16;" :: "r"(dst), "l"(src));
}
#define CP_COMMIT() asm volatile("cp.async.commit_group;")
#define CP_WAIT2()  asm volatile("cp.async.wait_group 2;")

#define MMAT(C, A, B) \
    asm volatile("mma.sync.aligned.m16n8k8.row.col.f32.tf32.tf32.f32 " \
        "{%0,%1,%2,%3},{%4,%5,%6,%7},{%8,%9},{%0,%1,%2,%3};" \
        : "+f"(C[0]), "+f"(C[1]), "+f"(C[2]), "+f"(C[3]) \
        : "r"(A[0]), "r"(A[1]), "r"(A[2]), "r"(A[3]), "r"(B[0]), "r"(B[1]))

#define MMAB(C, A, B) \
    asm volatile("mma.sync.aligned.m16n8k16.row.col.f32.bf16.bf16.f32 " \
        "{%0,%1,%2,%3},{%4,%5,%6,%7},{%8,%9},{%0,%1,%2,%3};" \
        : "+f"(C[0]), "+f"(C[1]), "+f"(C[2]), "+f"(C[3]) \
        : "r"(A[0]), "r"(A[1]), "r"(A[2]), "r"(A[3]), "r"(B[0]), "r"(B[1]))

// Cubic B-spline basis: grid[j] = 0.4*(j-3) - 1
__device__ __forceinline__ void bspline8(float x, float* o) {
    float bb[11];
#pragma unroll
    for (int j = 0; j < 11; j++) {
        float gA = 0.4f * (float)(j - 3) - 1.0f;
        float gB = 0.4f * (float)(j - 2) - 1.0f;
        bb[j] = (x >= gA && x < gB) ? 1.0f : 0.0f;
    }
#pragma unroll
    for (int k = 1; k <= 3; k++) {
        float inv = 1.0f / (0.4f * (float)k);
#pragma unroll
        for (int j = 0; j <= 10 - k; j++) {
            float gj = 0.4f * (float)(j - 3) - 1.0f;
            float gk = 0.4f * (float)(j + k - 2) - 1.0f;
            bb[j] = ((x - gj) * bb[j] + (gk - x) * bb[j + 1]) * inv;
        }
    }
#pragma unroll
    for (int m = 0; m < 8; m++) o[m] = bb[m];
}

// ---------------------------------------------------------------------------
// Prep: split X into bf16 hi|lo planes (4 elems/thread, 8B stores)
// ---------------------------------------------------------------------------
__global__ void prep_xe_kernel(const float* __restrict__ X) {
    int idx = blockIdx.x * 256 + threadIdx.x;   // over NROWS * 68
    if (idx >= NROWS * 68) return;
    int m = idx / 68, kp = (idx % 68) * 4;
    union { __nv_bfloat16 b[4]; uint2 u; } H, L;
#pragma unroll
    for (int j = 0; j < 4; j++) {
        int k = kp + j;
        float v = (k < INS) ? X[(size_t)m * INS + k] : 0.0f;
        __nv_bfloat16 hi = __float2bfloat16_rn(v);
        H.b[j] = hi;
        L.b[j] = __float2bfloat16_rn(v - __bfloat162float(hi));
    }
    *(uint2*)(g_Xe + (size_t)m * XSTR + kp)       = H.u;
    *(uint2*)(g_Xe + (size_t)m * XSTR + 272 + kp) = L.u;
}

// Prep: concat + split gate weights into bf16 hi|lo planes
__global__ void prep_wg_kernel(const float* __restrict__ Wf,
                               const float* __restrict__ Wb) {
    int idx = blockIdx.x * 256 + threadIdx.x;
    if (idx >= NGP * KP) return;
    int g = idx / KP, k = idx % KP;
    float v = 0.0f;
    if (g < NGATE && k < INS)
        v = (g < 240) ? Wf[(size_t)g * INS + k] : Wb[(size_t)(g - 240) * INS + k];
    __nv_bfloat16 hi = __float2bfloat16_rn(v);
    g_Wg[(size_t)g * XSTR + k]       = hi;
    g_Wg[(size_t)g * XSTR + 272 + k] = __float2bfloat16_rn(v - __bfloat162float(hi));
}

// Prep: tf32-rounded Wk = [base_weight | spline_weight*scaler], 257 full rows
__global__ void prep_wk_kernel(const float* __restrict__ base_w,
                               const float* __restrict__ spl_w,
                               const float* __restrict__ scaler) {
    int idx = blockIdx.x * 256 + threadIdx.x;
    if (idx >= OUTS * KEXP) return;
    int o = idx / KEXP, k = idx % KEXP;
    float v;
    if (k < 80) v = base_w[o * 80 + k];
    else {
        int q = k - 80;
        int i = q >> 3, m = q & 7;
        v = spl_w[(o * 80 + i) * 8 + m] * scaler[o * 80 + i];
    }
    g_Wk[idx] = tf32f(v);
}

// ---------------------------------------------------------------------------
// Kernel 1: gi = X * Wcat^T  (bf16 3-term, 256x128 block, cp.async 4-stage)
// ---------------------------------------------------------------------------
__global__ __launch_bounds__(256, 1)
void gemm_gi_kernel() {
    extern __shared__ __nv_bfloat16 smb[];
    const int tid = threadIdx.x, lane = tid & 31, w = tid >> 5;
    const int g = lane >> 2, c = lane & 3;
    const int wm = (w >> 1) * 64, wn = (w & 1) * 64;
    const int n0 = blockIdx.x * 128, m0 = blockIdx.y * 256;
    const uint32_t sb = (uint32_t)__cvta_generic_to_shared(smb);

    float acc[4][8][4];
#pragma unroll
    for (int i = 0; i < 4; i++)
#pragma unroll
        for (int j = 0; j < 8; j++)
#pragma unroll
            for (int l = 0; l < 4; l++) acc[i][j][l] = 0.0f;

    const int arow = tid >> 2, ach = tid & 3;
    const int asrc = (ach < 2) ? (ach * 8) : (272 + (ach - 2) * 8);
    const int adst = ach * 8;

    auto stage_copy = [&](int s, int t) {
        const int k0 = t * 16;
        const uint32_t abase = sb + (uint32_t)(s * GI_STG) * 2;
#pragma unroll
        for (int i = 0; i < 4; i++) {
            int row = arow + i * 64;
            cp16(abase + (uint32_t)(row * 40 + adst) * 2,
                 g_Xe + (size_t)(m0 + row) * XSTR + k0 + asrc);
        }
        const uint32_t bbase = abase + (uint32_t)GA * 2;
#pragma unroll
        for (int i = 0; i < 2; i++) {
            int row = arow + i * 64;
            cp16(bbase + (uint32_t)(row * 40 + adst) * 2,
                 g_Wg + (size_t)(n0 + row) * XSTR + k0 + asrc);
        }
    };

    const int NT = KP / 16;   // 17
#pragma unroll
    for (int s = 0; s < 3; s++) { stage_copy(s, s); CP_COMMIT(); }

    for (int t = 0; t < NT; t++) {
        CP_WAIT2();
        __syncthreads();
        if (t + 3 < NT) stage_copy((t + 3) & 3, t + 3);
        CP_COMMIT();

        const unsigned* Aw = (const unsigned*)(smb + (t & 3) * GI_STG);
        const unsigned* Bw = (const unsigned*)(smb + (t & 3) * GI_STG + GA);
        unsigned Ah[4][4], Al[4][4];
#pragma unroll
        for (int mt = 0; mt < 4; mt++) {
            const unsigned* p0 = Aw + (wm + mt * 16 + g) * 20;
            const unsigned* p1 = p0 + 8 * 20;
            Ah[mt][0] = p0[c];     Ah[mt][1] = p1[c];
            Ah[mt][2] = p0[c + 4]; Ah[mt][3] = p1[c + 4];
            Al[mt][0] = p0[8 + c];  Al[mt][1] = p1[8 + c];
            Al[mt][2] = p0[12 + c]; Al[mt][3] = p1[12 + c];
        }
#pragma unroll
        for (int nt = 0; nt < 8; nt++) {
            const unsigned* q = Bw + (wn + nt * 8 + g) * 20;
            unsigned bh[2] = {q[c], q[c + 4]};
            unsigned bl[2] = {q[8 + c], q[12 + c]};
#pragma unroll
            for (int mt = 0; mt < 4; mt++) {
                MMAB(acc[mt][nt], Ah[mt], bh);
                MMAB(acc[mt][nt], Al[mt], bh);
                MMAB(acc[mt][nt], Ah[mt], bl);
            }
        }
    }

#pragma unroll
    for (int mt = 0; mt < 4; mt++) {
        int r0 = m0 + wm + mt * 16 + g, r1 = r0 + 8;
#pragma unroll
        for (int nt = 0; nt < 8; nt++) {
            int o = n0 + wn + nt * 8 + 2 * c;
            if (o < NGATE) {
                float* C = acc[mt][nt];
                *(float2*)&g_gi[(size_t)r0 * NGATE + o] = make_float2(C[0], C[1]);
                *(float2*)&g_gi[(size_t)r1 * NGATE + o] = make_float2(C[2], C[3]);
            }
        }
    }
}

// ---------------------------------------------------------------------------
// Kernel 2: GRU cells + feature expansion + fused output column 256
// ---------------------------------------------------------------------------
__global__ __launch_bounds__(256)
void feat_kernel(const float* __restrict__ bih_f, const float* __restrict__ bhh_f,
                 const float* __restrict__ bih_b, const float* __restrict__ bhh_b,
                 const float* __restrict__ Whh_f, const float* __restrict__ Whh_b,
                 const float* __restrict__ slope, float* __restrict__ out) {
    __shared__ float sWf[40 * 120];
    __shared__ float sWb[40 * 120];
    __shared__ float sW256[KEXP];
    __shared__ float sh1f[4][40];
    __shared__ float sh1b[4][40];
    __shared__ float sred[4][2];

    const int tid = threadIdx.x, lane = tid & 31;
    for (int e = tid; e < 4800; e += 256) {
        int g = e / 40, j = e % 40;
        sWf[j * 120 + g] = Whh_f[4800 + e];
        sWb[j * 120 + g] = Whh_b[4800 + e];
    }
    for (int e = tid; e < KEXP; e += 256) sW256[e] = g_Wk[(size_t)256 * KEXP + e];
    __syncthreads();

    const int rl = tid >> 6;
    const int u  = tid & 63;
    const bool act = (u < HID);
    const float s256 = slope[256];

    float bf_r0=0, bf_z0=0, bf_n0=0, bb_r0=0, bb_z0=0, bb_n0=0;
    float if_r0=0, if_z0=0, if_n0=0, ib_r0=0, ib_z0=0, ib_n0=0;
    float bf_r1=0, bf_z1=0, bf_n1=0, bb_r1=0, bb_z1=0, bb_n1=0;
    float if_r1=0, if_z1=0, if_n1=0, ib_r1=0, ib_z1=0, ib_n1=0;
    if (act) {
        bf_r0 = bhh_f[u]; bf_z0 = bhh_f[40+u]; bf_n0 = bhh_f[80+u];
        bb_r0 = bhh_b[u]; bb_z0 = bhh_b[40+u]; bb_n0 = bhh_b[80+u];
        if_r0 = bih_f[u]; if_z0 = bih_f[40+u]; if_n0 = bih_f[80+u];
        ib_r0 = bih_b[u]; ib_z0 = bih_b[40+u]; ib_n0 = bih_b[80+u];
        bf_r1 = bhh_f[120+u]; bf_z1 = bhh_f[160+u]; bf_n1 = bhh_f[200+u];
        bb_r1 = bhh_b[120+u]; bb_z1 = bhh_b[160+u]; bb_n1 = bhh_b[200+u];
        if_r1 = bih_f[120+u]; if_z1 = bih_f[160+u]; if_n1 = bih_f[200+u];
        ib_r1 = bih_b[120+u]; ib_z1 = bih_b[160+u]; ib_n1 = bih_b[200+u];
    }

    for (int it = 0; it < 4; it++) {
        const int row = blockIdx.x * 16 + it * 4 + rl;
        const int b = row / TT, t = row % TT;
        const int row_rev = b * TT + (TT - 1 - t);
        const float* gf = g_gi + (size_t)row * NGATE;
        const float* gb = g_gi + (size_t)row_rev * NGATE;

        float h1f = 0.0f, h1b = 0.0f;
        if (act) {
            {
                float r = sigf(gf[u] + if_r0 + bf_r0);
                float z = sigf(gf[40 + u] + if_z0 + bf_z0);
                float n = tanhf(gf[80 + u] + if_n0 + r * bf_n0);
                h1f = (1.0f - z) * n;
                sh1f[rl][u] = h1f;
            }
            {
                float r = sigf(gb[240 + u] + ib_r0 + bb_r0);
                float z = sigf(gb[280 + u] + ib_z0 + bb_z0);
                float n = tanhf(gb[320 + u] + ib_n0 + r * bb_n0);
                h1b = (1.0f - z) * n;
                sh1b[rl][u] = h1b;
            }
        }
        __syncthreads();

        float part = 0.0f;
        if (act) {
            float gr = bf_r1, gz = bf_z1, gn = bf_n1;
#pragma unroll
            for (int j = 0; j < 40; j++) {
                float h = sh1f[rl][j];
                gr = fmaf(sWf[j * 120 + u],      h, gr);
                gz = fmaf(sWf[j * 120 + 40 + u], h, gz);
                gn = fmaf(sWf[j * 120 + 80 + u], h, gn);
            }
            float r = sigf(gf[120 + u] + if_r1 + gr);
            float z = sigf(gf[160 + u] + if_z1 + gz);
            float n = tanhf(gf[200 + u] + if_n1 + r * gn);
            float hf = (1.0f - z) * n + z * h1f;

            float br = bb_r1, bz = bb_z1, bn = bb_n1;
#pragma unroll
            for (int j = 0; j < 40; j++) {
                float h = sh1b[rl][j];
                br = fmaf(sWb[j * 120 + u],      h, br);
                bz = fmaf(sWb[j * 120 + 40 + u], h, bz);
                bn = fmaf(sWb[j * 120 + 80 + u], h, bn);
            }
            float r2 = sigf(gb[360 + u] + ib_r1 + br);
            float z2 = sigf(gb[400 + u] + ib_z1 + bz);
            float n2 = tanhf(gb[440 + u] + ib_n1 + r2 * bn);
            float hb = (1.0f - z2) * n2 + z2 * h1b;

            float* e = g_E + (size_t)row * KEXP;
            float e0 = tf32f(hf * sigf(hf));
            float e1 = tf32f(hb * sigf(hb));
            e[u]      = e0;
            e[40 + u] = e1;
            part = sW256[u] * e0 + sW256[40 + u] * e1;

            float bf[8], rv[8];
            bspline8(hf, bf);
#pragma unroll
            for (int j = 0; j < 8; j++) { rv[j] = tf32f(bf[j]); part = fmaf(sW256[80 + u * 8 + j], rv[j], part); }
            *(float4*)&e[80 + u * 8]     = make_float4(rv[0], rv[1], rv[2], rv[3]);
            *(float4*)&e[80 + u * 8 + 4] = make_float4(rv[4], rv[5], rv[6], rv[7]);

            bspline8(hb, bf);
#pragma unroll
            for (int j = 0; j < 8; j++) { rv[j] = tf32f(bf[j]); part = fmaf(sW256[80 + (40 + u) * 8 + j], rv[j], part); }
            *(float4*)&e[80 + (40 + u) * 8]     = make_float4(rv[0], rv[1], rv[2], rv[3]);
            *(float4*)&e[80 + (40 + u) * 8 + 4] = make_float4(rv[4], rv[5], rv[6], rv[7]);
        }

        // reduce col-256 partial across the 64-lane row group (2 warps)
        float tot = part;
#pragma unroll
        for (int off = 16; off; off >>= 1) tot += __shfl_xor_sync(0xffffffffu, tot, off);
        if (lane == 0) sred[rl][(tid >> 5) & 1] = tot;
        __syncthreads();
        if (u == 0)
            out[(size_t)row * OUTS + 256] = 1.2f * sigf(s256 * (sred[rl][0] + sred[rl][1]));
    }
}

// ---------------------------------------------------------------------------
// Kernel 3: out[:,0:256] = 1.2*sigmoid(slope*(E*Wk^T))  (tf32, cp.async 4-stage)
// ---------------------------------------------------------------------------
__global__ __launch_bounds__(256, 1)
void gemm_kan_kernel(const float* __restrict__ slope, float* __restrict__ out) {
    extern __shared__ float smf[];
    const int tid = threadIdx.x, lane = tid & 31, w = tid >> 5;
    const int g = lane >> 2, c = lane & 3;
    const int wm = (w >> 1) * 64, wn = (w & 1) * 64;
    const int n0 = blockIdx.x * 128, m0 = blockIdx.y * 256;
    const uint32_t sb = (uint32_t)__cvta_generic_to_shared(smf);

    float acc[4][8][4];
#pragma unroll
    for (int i = 0; i < 4; i++)
#pragma unroll
        for (int j = 0; j < 8; j++)
#pragma unroll
            for (int l = 0; l < 4; l++) acc[i][j][l] = 0.0f;

    const int arow = tid >> 2, ach = tid & 3;

    auto stage_copy = [&](int s, int t) {
        const int k0 = t * 16;
        const uint32_t abase = sb + (uint32_t)(s * KAN_STG) * 4;
#pragma unroll
        for (int i = 0; i < 4; i++) {
            int row = arow + i * 64;
            cp16(abase + (uint32_t)(row * 20 + ach * 4) * 4,
                 g_E + (size_t)(m0 + row) * KEXP + k0 + ach * 4);
        }
        const uint32_t bbase = abase + (uint32_t)KA * 4;
#pragma unroll
        for (int i = 0; i < 2; i++) {
            int row = arow + i * 64;
            cp16(bbase + (uint32_t)(row * 20 + ach * 4) * 4,
                 g_Wk + (size_t)(n0 + row) * KEXP + k0 + ach * 4);
        }
    };

    const int NT = KEXP / 16;   // 45
#pragma unroll
    for (int s = 0; s < 3; s++) { stage_copy(s, s); CP_COMMIT(); }

    for (int t = 0; t < NT; t++) {
        CP_WAIT2();
        __syncthreads();
        if (t + 3 < NT) stage_copy((t + 3) & 3, t + 3);
        CP_COMMIT();

        const float* Ac = smf + (t & 3) * KAN_STG;
        const float* Bc = smf + (t & 3) * KAN_STG + KA;
#pragma unroll
        for (int ks = 0; ks < 2; ks++) {
            const int kc = ks * 8 + c;
            unsigned a[4][4];
#pragma unroll
            for (int mt = 0; mt < 4; mt++) {
                const float* p0 = Ac + (wm + mt * 16 + g) * 20;
                const float* p1 = p0 + 8 * 20;
                a[mt][0] = __float_as_uint(p0[kc]);
                a[mt][1] = __float_as_uint(p1[kc]);
                a[mt][2] = __float_as_uint(p0[kc + 4]);
                a[mt][3] = __float_as_uint(p1[kc + 4]);
            }
#pragma unroll
            for (int nt = 0; nt < 8; nt++) {
                const float* q = Bc + (wn + nt * 8 + g) * 20;
                unsigned b[2] = {__float_as_uint(q[kc]), __float_as_uint(q[kc + 4])};
#pragma unroll
                for (int mt = 0; mt < 4; mt++)
                    MMAT(acc[mt][nt], a[mt], b);
            }
        }
    }

    // epilogue: all columns valid (o <= 254 < 257)
#pragma unroll
    for (int mt = 0; mt < 4; mt++) {
        int r0 = m0 + wm + mt * 16 + g, r1 = r0 + 8;
#pragma unroll
        for (int nt = 0; nt < 8; nt++) {
            int o = n0 + wn + nt * 8 + 2 * c;
            float* C = acc[mt][nt];
            float s0 = __ldg(&slope[o]), s1 = __ldg(&slope[o + 1]);
            out[(size_t)r0 * OUTS + o]     = 1.2f * sigf(s0 * C[0]);
            out[(size_t)r0 * OUTS + o + 1] = 1.2f * sigf(s1 * C[1]);
            out[(size_t)r1 * OUTS + o]     = 1.2f * sigf(s0 * C[2]);
            out[(size_t)r1 * OUTS + o + 1] = 1.2f * sigf(s1 * C[3]);
        }
    }
}

// ---------------------------------------------------------------------------
extern "C" void kernel_launch(void* const* d_in, const int* in_sizes, int n_in,
                              void* d_out, int out_size) {
    const float* x      = (const float*)d_in[0];
    const float* Wih_f  = (const float*)d_in[1];
    const float* Whh_f  = (const float*)d_in[2];
    const float* bih_f  = (const float*)d_in[3];
    const float* bhh_f  = (const float*)d_in[4];
    const float* Wih_b  = (const float*)d_in[5];
    const float* Whh_b  = (const float*)d_in[6];
    const float* bih_b  = (const float*)d_in[7];
    const float* bhh_b  = (const float*)d_in[8];
    const float* base_w = (const float*)d_in[9];
    const float* spl_w  = (const float*)d_in[10];
    const float* scaler = (const float*)d_in[11];
    const float* slope  = (const float*)d_in[12];
    float* out = (float*)d_out;

    cudaFuncSetAttribute(gemm_gi_kernel,  cudaFuncAttributeMaxDynamicSharedMemorySize, SMEM_BYTES);
    cudaFuncSetAttribute(gemm_kan_kernel, cudaFuncAttributeMaxDynamicSharedMemorySize, SMEM_BYTES);

    prep_xe_kernel<<<(NROWS * 68 + 255) / 256, 256>>>(x);
    prep_wg_kernel<<<(NGP * KP + 255) / 256, 256>>>(Wih_f, Wih_b);
    prep_wk_kernel<<<(OUTS * KEXP + 255) / 256, 256>>>(base_w, spl_w, scaler);

    gemm_gi_kernel<<<dim3(NGP / 128, NROWS / 256), 256, SMEM_BYTES>>>();
    feat_kernel<<<NROWS / 16, 256>>>(bih_f, bhh_f, bih_b, bhh_b, Whh_f, Whh_b, slope, out);
    gemm_kan_kernel<<<dim3(OUTN / 128, NROWS / 256), 256, SMEM_BYTES>>>(slope, out);
}

// round 10
// speedup vs baseline: 2.6659x; 1.0593x over previous
#include <cuda_runtime.h>
#include <cuda_bf16.h>
#include <cstdint>

// Problem constants
#define NROWS   64000      // B*T
#define TT      1000
#define INS     257
#define KP      272        // padded K for gate GEMM
#define XSTR    544        // Xe row stride in bf16: [hi 272 | lo 272]
#define HID     40
#define NGATE   480
#define NGP     512        // padded N for gate GEMM
#define KEXP    720
#define OUTS    257
#define OUTN    256        // KAN GEMM covers cols 0..255; col 256 fused into feat

// gi smem (bf16 elems): per stage A 128x40, B 128x40
#define GA_E 5120
#define GI_STG 10240       // elems per stage (A+B)
// kan smem (f32 elems): per stage A 128x20, B 128x20
#define KA_E 2560
#define KAN_STG 5120       // floats per stage
#define SMEM_BYTES 81920   // 4 stages, both kernels (bytes)

// Static device scratch
__device__ __nv_bfloat16 g_Xe[(size_t)NROWS * XSTR];   // 69.6 MB
__device__ __nv_bfloat16 g_Wg[(size_t)NGP * XSTR];
__device__ float g_gi[(size_t)NROWS * NGATE];          // 122.9 MB
__device__ float g_E [(size_t)NROWS * KEXP];           // 184.3 MB (tf32-rounded)
__device__ float g_Wk[(size_t)OUTS * KEXP];            // tf32-rounded, 257 rows

__device__ __forceinline__ float sigf(float x) { return 1.0f / (1.0f + __expf(-x)); }
__device__ __forceinline__ unsigned tf32u(float v) {
    unsigned u; asm("cvt.rna.tf32.f32 %0, %1;" : "=r"(u) : "f"(v)); return u;
}
__device__ __forceinline__ float tf32f(float v) { return __uint_as_float(tf32u(v)); }

__device__ __forceinline__ void cp16(uint32_t dst, const void* src) {
    asm volatile("cp.async.cg.shared.global [%0], [%1], 16;" :: "r"(dst), "l"(src));
}
#define CP_COMMIT() asm volatile("cp.async.commit_group;")
#define CP_WAIT2()  asm volatile("cp.async.wait_group 2;")

#define MMAT(C, A, B) \
    asm volatile("mma.sync.aligned.m16n8k8.row.col.f32.tf32.tf32.f32 " \
        "{%0,%1,%2,%3},{%4,%5,%6,%7},{%8,%9},{%0,%1,%2,%3};" \
        : "+f"(C[0]), "+f"(C[1]), "+f"(C[2]), "+f"(C[3]) \
        : "r"(A[0]), "r"(A[1]), "r"(A[2]), "r"(A[3]), "r"(B[0]), "r"(B[1]))

#define MMAB(C, A, B) \
    asm volatile("mma.sync.aligned.m16n8k16.row.col.f32.bf16.bf16.f32 " \
        "{%0,%1,%2,%3},{%4,%5,%6,%7},{%8,%9},{%0,%1,%2,%3};" \
        : "+f"(C[0]), "+f"(C[1]), "+f"(C[2]), "+f"(C[3]) \
        : "r"(A[0]), "r"(A[1]), "r"(A[2]), "r"(A[3]), "r"(B[0]), "r"(B[1]))

// Cubic B-spline basis: grid[j] = 0.4*(j-3) - 1
__device__ __forceinline__ void bspline8(float x, float* o) {
    float bb[11];
#pragma unroll
    for (int j = 0; j < 11; j++) {
        float gA = 0.4f * (float)(j - 3) - 1.0f;
        float gB = 0.4f * (float)(j - 2) - 1.0f;
        bb[j] = (x >= gA && x < gB) ? 1.0f : 0.0f;
    }
#pragma unroll
    for (int k = 1; k <= 3; k++) {
        float inv = 1.0f / (0.4f * (float)k);
#pragma unroll
        for (int j = 0; j <= 10 - k; j++) {
            float gj = 0.4f * (float)(j - 3) - 1.0f;
            float gk = 0.4f * (float)(j + k - 2) - 1.0f;
            bb[j] = ((x - gj) * bb[j] + (gk - x) * bb[j + 1]) * inv;
        }
    }
#pragma unroll
    for (int m = 0; m < 8; m++) o[m] = bb[m];
}

// ---------------------------------------------------------------------------
// Prep: split X into bf16 hi|lo planes (4 elems/thread, 8B stores)
// ---------------------------------------------------------------------------
__global__ void prep_xe_kernel(const float* __restrict__ X) {
    int idx = blockIdx.x * 256 + threadIdx.x;   // over NROWS * 68
    if (idx >= NROWS * 68) return;
    int m = idx / 68, kp = (idx % 68) * 4;
    union { __nv_bfloat16 b[4]; uint2 u; } H, L;
#pragma unroll
    for (int j = 0; j < 4; j++) {
        int k = kp + j;
        float v = (k < INS) ? X[(size_t)m * INS + k] : 0.0f;
        __nv_bfloat16 hi = __float2bfloat16_rn(v);
        H.b[j] = hi;
        L.b[j] = __float2bfloat16_rn(v - __bfloat162float(hi));
    }
    *(uint2*)(g_Xe + (size_t)m * XSTR + kp)       = H.u;
    *(uint2*)(g_Xe + (size_t)m * XSTR + 272 + kp) = L.u;
}

// Prep: concat + split gate weights into bf16 hi|lo planes
__global__ void prep_wg_kernel(const float* __restrict__ Wf,
                               const float* __restrict__ Wb) {
    int idx = blockIdx.x * 256 + threadIdx.x;
    if (idx >= NGP * KP) return;
    int g = idx / KP, k = idx % KP;
    float v = 0.0f;
    if (g < NGATE && k < INS)
        v = (g < 240) ? Wf[(size_t)g * INS + k] : Wb[(size_t)(g - 240) * INS + k];
    __nv_bfloat16 hi = __float2bfloat16_rn(v);
    g_Wg[(size_t)g * XSTR + k]       = hi;
    g_Wg[(size_t)g * XSTR + 272 + k] = __float2bfloat16_rn(v - __bfloat162float(hi));
}

// Prep: tf32-rounded Wk = [base_weight | spline_weight*scaler], 257 full rows
__global__ void prep_wk_kernel(const float* __restrict__ base_w,
                               const float* __restrict__ spl_w,
                               const float* __restrict__ scaler) {
    int idx = blockIdx.x * 256 + threadIdx.x;
    if (idx >= OUTS * KEXP) return;
    int o = idx / KEXP, k = idx % KEXP;
    float v;
    if (k < 80) v = base_w[o * 80 + k];
    else {
        int q = k - 80;
        int i = q >> 3, m = q & 7;
        v = spl_w[(o * 80 + i) * 8 + m] * scaler[o * 80 + i];
    }
    g_Wk[idx] = tf32f(v);
}

// ---------------------------------------------------------------------------
// Kernel 1: gi = X * Wcat^T  (bf16 3-term, 128x128 block, 4 warps, 2 CTA/SM)
// ---------------------------------------------------------------------------
__global__ __launch_bounds__(128, 2)
void gemm_gi_kernel() {
    extern __shared__ __nv_bfloat16 smb[];
    const int tid = threadIdx.x, lane = tid & 31, w = tid >> 5;
    const int g = lane >> 2, c = lane & 3;
    const int wm = (w >> 1) * 64, wn = (w & 1) * 64;
    const int n0 = blockIdx.x * 128, m0 = blockIdx.y * 128;
    const uint32_t sb = (uint32_t)__cvta_generic_to_shared(smb);

    float acc[4][8][4];
#pragma unroll
    for (int i = 0; i < 4; i++)
#pragma unroll
        for (int j = 0; j < 8; j++)
#pragma unroll
            for (int l = 0; l < 4; l++) acc[i][j][l] = 0.0f;

    const int arow = tid >> 2, ach = tid & 3;
    const int asrc = (ach < 2) ? (ach * 8) : (272 + (ach - 2) * 8);
    const int adst = ach * 8;

    auto stage_copy = [&](int s, int t) {
        const int k0 = t * 16;
        const uint32_t abase = sb + (uint32_t)(s * GI_STG) * 2;
#pragma unroll
        for (int i = 0; i < 4; i++) {
            int row = arow + i * 32;
            cp16(abase + (uint32_t)(row * 40 + adst) * 2,
                 g_Xe + (size_t)(m0 + row) * XSTR + k0 + asrc);
        }
        const uint32_t bbase = abase + (uint32_t)GA_E * 2;
#pragma unroll
        for (int i = 0; i < 4; i++) {
            int row = arow + i * 32;
            cp16(bbase + (uint32_t)(row * 40 + adst) * 2,
                 g_Wg + (size_t)(n0 + row) * XSTR + k0 + asrc);
        }
    };

    const int NT = KP / 16;   // 17
#pragma unroll
    for (int s = 0; s < 3; s++) { stage_copy(s, s); CP_COMMIT(); }

    for (int t = 0; t < NT; t++) {
        CP_WAIT2();
        __syncthreads();
        if (t + 3 < NT) stage_copy((t + 3) & 3, t + 3);
        CP_COMMIT();

        const unsigned* Aw = (const unsigned*)(smb + (t & 3) * GI_STG);
        const unsigned* Bw = (const unsigned*)(smb + (t & 3) * GI_STG + GA_E);
        unsigned Ah[4][4], Al[4][4];
#pragma unroll
        for (int mt = 0; mt < 4; mt++) {
            const unsigned* p0 = Aw + (wm + mt * 16 + g) * 20;
            const unsigned* p1 = p0 + 8 * 20;
            Ah[mt][0] = p0[c];     Ah[mt][1] = p1[c];
            Ah[mt][2] = p0[c + 4]; Ah[mt][3] = p1[c + 4];
            Al[mt][0] = p0[8 + c];  Al[mt][1] = p1[8 + c];
            Al[mt][2] = p0[12 + c]; Al[mt][3] = p1[12 + c];
        }
#pragma unroll
        for (int nt = 0; nt < 8; nt++) {
            const unsigned* q = Bw + (wn + nt * 8 + g) * 20;
            unsigned bh[2] = {q[c], q[c + 4]};
            unsigned bl[2] = {q[8 + c], q[12 + c]};
#pragma unroll
            for (int mt = 0; mt < 4; mt++) {
                MMAB(acc[mt][nt], Ah[mt], bh);
                MMAB(acc[mt][nt], Al[mt], bh);
                MMAB(acc[mt][nt], Ah[mt], bl);
            }
        }
    }

#pragma unroll
    for (int mt = 0; mt < 4; mt++) {
        int r0 = m0 + wm + mt * 16 + g, r1 = r0 + 8;
#pragma unroll
        for (int nt = 0; nt < 8; nt++) {
            int o = n0 + wn + nt * 8 + 2 * c;
            if (o < NGATE) {
                float* C = acc[mt][nt];
                *(float2*)&g_gi[(size_t)r0 * NGATE + o] = make_float2(C[0], C[1]);
                *(float2*)&g_gi[(size_t)r1 * NGATE + o] = make_float2(C[2], C[3]);
            }
        }
    }
}

// ---------------------------------------------------------------------------
// Kernel 2: GRU cells + feature expansion + fused output column 256
// ---------------------------------------------------------------------------
__global__ __launch_bounds__(256)
void feat_kernel(const float* __restrict__ bih_f, const float* __restrict__ bhh_f,
                 const float* __restrict__ bih_b, const float* __restrict__ bhh_b,
                 const float* __restrict__ Whh_f, const float* __restrict__ Whh_b,
                 const float* __restrict__ slope, float* __restrict__ out) {
    __shared__ float sWf[40 * 120];
    __shared__ float sWb[40 * 120];
    __shared__ float sW256[KEXP];
    __shared__ float sh1f[4][40];
    __shared__ float sh1b[4][40];
    __shared__ float sred[4][2];

    const int tid = threadIdx.x, lane = tid & 31;
    for (int e = tid; e < 4800; e += 256) {
        int g = e / 40, j = e % 40;
        sWf[j * 120 + g] = Whh_f[4800 + e];
        sWb[j * 120 + g] = Whh_b[4800 + e];
    }
    for (int e = tid; e < KEXP; e += 256) sW256[e] = g_Wk[(size_t)256 * KEXP + e];
    __syncthreads();

    const int rl = tid >> 6;
    const int u  = tid & 63;
    const bool act = (u < HID);
    const float s256 = slope[256];

    float bf_r0=0, bf_z0=0, bf_n0=0, bb_r0=0, bb_z0=0, bb_n0=0;
    float if_r0=0, if_z0=0, if_n0=0, ib_r0=0, ib_z0=0, ib_n0=0;
    float bf_r1=0, bf_z1=0, bf_n1=0, bb_r1=0, bb_z1=0, bb_n1=0;
    float if_r1=0, if_z1=0, if_n1=0, ib_r1=0, ib_z1=0, ib_n1=0;
    if (act) {
        bf_r0 = bhh_f[u]; bf_z0 = bhh_f[40+u]; bf_n0 = bhh_f[80+u];
        bb_r0 = bhh_b[u]; bb_z0 = bhh_b[40+u]; bb_n0 = bhh_b[80+u];
        if_r0 = bih_f[u]; if_z0 = bih_f[40+u]; if_n0 = bih_f[80+u];
        ib_r0 = bih_b[u]; ib_z0 = bih_b[40+u]; ib_n0 = bih_b[80+u];
        bf_r1 = bhh_f[120+u]; bf_z1 = bhh_f[160+u]; bf_n1 = bhh_f[200+u];
        bb_r1 = bhh_b[120+u]; bb_z1 = bhh_b[160+u]; bb_n1 = bhh_b[200+u];
        if_r1 = bih_f[120+u]; if_z1 = bih_f[160+u]; if_n1 = bih_f[200+u];
        ib_r1 = bih_b[120+u]; ib_z1 = bih_b[160+u]; ib_n1 = bih_b[200+u];
    }

    for (int it = 0; it < 4; it++) {
        const int row = blockIdx.x * 16 + it * 4 + rl;
        const int b = row / TT, t = row % TT;
        const int row_rev = b * TT + (TT - 1 - t);
        const float* gf = g_gi + (size_t)row * NGATE;
        const float* gb = g_gi + (size_t)row_rev * NGATE;

        float h1f = 0.0f, h1b = 0.0f;
        if (act) {
            {
                float r = sigf(gf[u] + if_r0 + bf_r0);
                float z = sigf(gf[40 + u] + if_z0 + bf_z0);
                float n = tanhf(gf[80 + u] + if_n0 + r * bf_n0);
                h1f = (1.0f - z) * n;
                sh1f[rl][u] = h1f;
            }
            {
                float r = sigf(gb[240 + u] + ib_r0 + bb_r0);
                float z = sigf(gb[280 + u] + ib_z0 + bb_z0);
                float n = tanhf(gb[320 + u] + ib_n0 + r * bb_n0);
                h1b = (1.0f - z) * n;
                sh1b[rl][u] = h1b;
            }
        }
        __syncthreads();

        float part = 0.0f;
        if (act) {
            float gr = bf_r1, gz = bf_z1, gn = bf_n1;
#pragma unroll
            for (int j = 0; j < 40; j++) {
                float h = sh1f[rl][j];
                gr = fmaf(sWf[j * 120 + u],      h, gr);
                gz = fmaf(sWf[j * 120 + 40 + u], h, gz);
                gn = fmaf(sWf[j * 120 + 80 + u], h, gn);
            }
            float r = sigf(gf[120 + u] + if_r1 + gr);
            float z = sigf(gf[160 + u] + if_z1 + gz);
            float n = tanhf(gf[200 + u] + if_n1 + r * gn);
            float hf = (1.0f - z) * n + z * h1f;

            float br = bb_r1, bz = bb_z1, bn = bb_n1;
#pragma unroll
            for (int j = 0; j < 40; j++) {
                float h = sh1b[rl][j];
                br = fmaf(sWb[j * 120 + u],      h, br);
                bz = fmaf(sWb[j * 120 + 40 + u], h, bz);
                bn = fmaf(sWb[j * 120 + 80 + u], h, bn);
            }
            float r2 = sigf(gb[360 + u] + ib_r1 + br);
            float z2 = sigf(gb[400 + u] + ib_z1 + bz);
            float n2 = tanhf(gb[440 + u] + ib_n1 + r2 * bn);
            float hb = (1.0f - z2) * n2 + z2 * h1b;

            float* e = g_E + (size_t)row * KEXP;
            float e0 = tf32f(hf * sigf(hf));
            float e1 = tf32f(hb * sigf(hb));
            e[u]      = e0;
            e[40 + u] = e1;
            part = sW256[u] * e0 + sW256[40 + u] * e1;

            float bf[8], rv[8];
            bspline8(hf, bf);
#pragma unroll
            for (int j = 0; j < 8; j++) { rv[j] = tf32f(bf[j]); part = fmaf(sW256[80 + u * 8 + j], rv[j], part); }
            *(float4*)&e[80 + u * 8]     = make_float4(rv[0], rv[1], rv[2], rv[3]);
            *(float4*)&e[80 + u * 8 + 4] = make_float4(rv[4], rv[5], rv[6], rv[7]);

            bspline8(hb, bf);
#pragma unroll
            for (int j = 0; j < 8; j++) { rv[j] = tf32f(bf[j]); part = fmaf(sW256[80 + (40 + u) * 8 + j], rv[j], part); }
            *(float4*)&e[80 + (40 + u) * 8]     = make_float4(rv[0], rv[1], rv[2], rv[3]);
            *(float4*)&e[80 + (40 + u) * 8 + 4] = make_float4(rv[4], rv[5], rv[6], rv[7]);
        }

        // reduce col-256 partial across the 64-lane row group (2 warps)
        float tot = part;
#pragma unroll
        for (int off = 16; off; off >>= 1) tot += __shfl_xor_sync(0xffffffffu, tot, off);
        if (lane == 0) sred[rl][(tid >> 5) & 1] = tot;
        __syncthreads();
        if (u == 0)
            out[(size_t)row * OUTS + 256] = 1.2f * sigf(s256 * (sred[rl][0] + sred[rl][1]));
    }
}

// ---------------------------------------------------------------------------
// Kernel 3: out[:,0:256] = 1.2*sigmoid(slope*(E*Wk^T))  (tf32, 128x128, 2 CTA/SM)
// ---------------------------------------------------------------------------
__global__ __launch_bounds__(128, 2)
void gemm_kan_kernel(const float* __restrict__ slope, float* __restrict__ out) {
    extern __shared__ float smf[];
    const int tid = threadIdx.x, lane = tid & 31, w = tid >> 5;
    const int g = lane >> 2, c = lane & 3;
    const int wm = (w >> 1) * 64, wn = (w & 1) * 64;
    const int n0 = blockIdx.x * 128, m0 = blockIdx.y * 128;
    const uint32_t sb = (uint32_t)__cvta_generic_to_shared(smf);

    float acc[4][8][4];
#pragma unroll
    for (int i = 0; i < 4; i++)
#pragma unroll
        for (int j = 0; j < 8; j++)
#pragma unroll
            for (int l = 0; l < 4; l++) acc[i][j][l] = 0.0f;

    const int arow = tid >> 2, ach = tid & 3;

    auto stage_copy = [&](int s, int t) {
        const int k0 = t * 16;
        const uint32_t abase = sb + (uint32_t)(s * KAN_STG) * 4;
#pragma unroll
        for (int i = 0; i < 4; i++) {
            int row = arow + i * 32;
            cp16(abase + (uint32_t)(row * 20 + ach * 4) * 4,
                 g_E + (size_t)(m0 + row) * KEXP + k0 + ach * 4);
        }
        const uint32_t bbase = abase + (uint32_t)KA_E * 4;
#pragma unroll
        for (int i = 0; i < 4; i++) {
            int row = arow + i * 32;
            cp16(bbase + (uint32_t)(row * 20 + ach * 4) * 4,
                 g_Wk + (size_t)(n0 + row) * KEXP + k0 + ach * 4);
        }
    };

    const int NT = KEXP / 16;   // 45
#pragma unroll
    for (int s = 0; s < 3; s++) { stage_copy(s, s); CP_COMMIT(); }

    for (int t = 0; t < NT; t++) {
        CP_WAIT2();
        __syncthreads();
        if (t + 3 < NT) stage_copy((t + 3) & 3, t + 3);
        CP_COMMIT();

        const float* Ac = smf + (t & 3) * KAN_STG;
        const float* Bc = smf + (t & 3) * KAN_STG + KA_E;
#pragma unroll
        for (int ks = 0; ks < 2; ks++) {
            const int kc = ks * 8 + c;
            unsigned a[4][4];
#pragma unroll
            for (int mt = 0; mt < 4; mt++) {
                const float* p0 = Ac + (wm + mt * 16 + g) * 20;
                const float* p1 = p0 + 8 * 20;
                a[mt][0] = __float_as_uint(p0[kc]);
                a[mt][1] = __float_as_uint(p1[kc]);
                a[mt][2] = __float_as_uint(p0[kc + 4]);
                a[mt][3] = __float_as_uint(p1[kc + 4]);
            }
#pragma unroll
            for (int nt = 0; nt < 8; nt++) {
                const float* q = Bc + (wn + nt * 8 + g) * 20;
                unsigned b[2] = {__float_as_uint(q[kc]), __float_as_uint(q[kc + 4])};
#pragma unroll
                for (int mt = 0; mt < 4; mt++)
                    MMAT(acc[mt][nt], a[mt], b);
            }
        }
    }

    // epilogue: all columns valid (o <= 255 < 257)
#pragma unroll
    for (int mt = 0; mt < 4; mt++) {
        int r0 = m0 + wm + mt * 16 + g, r1 = r0 + 8;
#pragma unroll
        for (int nt = 0; nt < 8; nt++) {
            int o = n0 + wn + nt * 8 + 2 * c;
            float* C = acc[mt][nt];
            float s0 = __ldg(&slope[o]), s1 = __ldg(&slope[o + 1]);
            out[(size_t)r0 * OUTS + o]     = 1.2f * sigf(s0 * C[0]);
            out[(size_t)r0 * OUTS + o + 1] = 1.2f * sigf(s1 * C[1]);
            out[(size_t)r1 * OUTS + o]     = 1.2f * sigf(s0 * C[2]);
            out[(size_t)r1 * OUTS + o + 1] = 1.2f * sigf(s1 * C[3]);
        }
    }
}

// ---------------------------------------------------------------------------
extern "C" void kernel_launch(void* const* d_in, const int* in_sizes, int n_in,
                              void* d_out, int out_size) {
    const float* x      = (const float*)d_in[0];
    const float* Wih_f  = (const float*)d_in[1];
    const float* Whh_f  = (const float*)d_in[2];
    const float* bih_f  = (const float*)d_in[3];
    const float* bhh_f  = (const float*)d_in[4];
    const float* Wih_b  = (const float*)d_in[5];
    const float* Whh_b  = (const float*)d_in[6];
    const float* bih_b  = (const float*)d_in[7];
    const float* bhh_b  = (const float*)d_in[8];
    const float* base_w = (const float*)d_in[9];
    const float* spl_w  = (const float*)d_in[10];
    const float* scaler = (const float*)d_in[11];
    const float* slope  = (const float*)d_in[12];
    float* out = (float*)d_out;

    cudaFuncSetAttribute(gemm_gi_kernel,  cudaFuncAttributeMaxDynamicSharedMemorySize, SMEM_BYTES);
    cudaFuncSetAttribute(gemm_kan_kernel, cudaFuncAttributeMaxDynamicSharedMemorySize, SMEM_BYTES);

    prep_xe_kernel<<<(NROWS * 68 + 255) / 256, 256>>>(x);
    prep_wg_kernel<<<(NGP * KP + 255) / 256, 256>>>(Wih_f, Wih_b);
    prep_wk_kernel<<<(OUTS * KEXP + 255) / 256, 256>>>(base_w, spl_w, scaler);

    gemm_gi_kernel<<<dim3(NGP / 128, NROWS / 128), 128, SMEM_BYTES>>>();
    feat_kernel<<<NROWS / 16, 256>>>(bih_f, bhh_f, bih_b, bhh_b, Whh_f, Whh_b, slope, out);
    gemm_kan_kernel<<<dim3(OUTN / 128, NROWS / 128), 128, SMEM_BYTES>>>(slope, out);
}